// round 2
// baseline (speedup 1.0000x reference)
#include <cuda_runtime.h>
#include <math.h>

#define BATCH 2
#define NPTS  2048
#define NS    64
#define MPOS  (NS * NPTS)   // 131072 positions per batch
#define C1    96
#define C3    192
#define GRP   8
#define R2    0.09f

// ---------------------------------------------------------------------------
// Static device scratch (allocation-free per harness rules)
// ---------------------------------------------------------------------------
__device__ __align__(256) int    d_idx[BATCH * NS * NPTS];                    // [b][s][n]
__device__ __align__(256) float  d_h1[(size_t)BATCH * C1 * MPOS];             // raw conv1 out [b][c][m]
__device__ __align__(256) float  d_h2[(size_t)BATCH * C1 * MPOS];             // raw conv2 out
__device__ __align__(256) float  d_h3[(size_t)BATCH * C3 * MPOS];             // raw conv3 out
__device__ __align__(256) float  d_pool[(size_t)BATCH * C3 * NPTS];           // pooled [b][c][n]
__device__ __align__(256) float  d_p1[(size_t)BATCH * C3 * NPTS];             // raw post1 out
__device__ __align__(256) float  d_p2[(size_t)BATCH * C1 * NPTS];             // raw post2 out
__device__ __align__(256) double d_stats[5 * BATCH * GRP * 2];                // sum,sumsq per stage
__device__ __align__(256) float  d_mr[5 * BATCH * GRP * 2];                   // mean,rstd per stage

// ---------------------------------------------------------------------------
// Zero the stats accumulators (must run at the start of every graph replay)
// ---------------------------------------------------------------------------
__global__ void zero_stats_kernel() {
    int t = threadIdx.x;
    if (t < 5 * BATCH * GRP * 2) d_stats[t] = 0.0;
}

// ---------------------------------------------------------------------------
// Ball query: one warp per point. First NS in-radius indices in ascending j,
// padded with the first hit. Matches sort(where(sq>r2, N, arange))[:NS].
// ---------------------------------------------------------------------------
__global__ void ballquery_kernel(const float* __restrict__ xyz) {
    int warp = (blockIdx.x * blockDim.x + threadIdx.x) >> 5;
    int lane = threadIdx.x & 31;
    if (warp >= BATCH * NPTS) return;
    int b = warp / NPTS, i = warp % NPTS;
    const float* base = xyz + (size_t)b * NPTS * 3;
    float cx = base[i * 3 + 0], cy = base[i * 3 + 1], cz = base[i * 3 + 2];
    int count = 0;
    int first = 0;
    for (int jb = 0; jb < NPTS; jb += 32) {
        int j = jb + lane;
        float dx = base[j * 3 + 0] - cx;
        float dy = base[j * 3 + 1] - cy;
        float dz = base[j * 3 + 2] - cz;
        float d2 = dx * dx + dy * dy + dz * dz;
        bool ok = (d2 <= R2);
        unsigned mask = __ballot_sync(0xffffffffu, ok);
        if (ok) {
            int pos = count + __popc(mask & ((1u << lane) - 1u));
            if (pos < NS) d_idx[((size_t)(b * NS + pos)) * NPTS + i] = j;
        }
        if (count == 0 && mask) first = jb + __ffs(mask) - 1;
        count += __popc(mask);
        if (count >= NS) break;
    }
    for (int p = count + lane; p < NS; p += 32)
        d_idx[((size_t)(b * NS + p)) * NPTS + i] = first;
}

// ---------------------------------------------------------------------------
// Conv1 (6 -> 96) fused with feature construction + stage-0 GN stats.
// One thread per (b, m=(s,n)). Writes raw h1 [b][c][m].
// ---------------------------------------------------------------------------
__global__ void conv1_kernel(const float* __restrict__ xyz,
                             const float* __restrict__ w1,
                             const float* __restrict__ b1,
                             double* __restrict__ stats0) {
    __shared__ float ws[C1 * 6];
    __shared__ float bs[C1];
    __shared__ float red[8][16];
    int tid = threadIdx.x;
    for (int i = tid; i < C1 * 6; i += 256) ws[i] = w1[i];
    if (tid < C1) bs[tid] = b1[tid];
    __syncthreads();

    int q = blockIdx.x * 256 + tid;
    int b = q / MPOS, m = q % MPOS;
    int s = m / NPTS, n = m % NPTS;
    int j = d_idx[((size_t)(b * NS + s)) * NPTS + n];
    const float* xb = xyz + (size_t)b * NPTS * 3;
    float f0 = xb[n * 3 + 0], f1 = xb[n * 3 + 1], f2 = xb[n * 3 + 2];
    float f3 = xb[j * 3 + 0] - f0, f4 = xb[j * 3 + 1] - f1, f5 = xb[j * 3 + 2] - f2;

    float sum8[8], sq8[8];
#pragma unroll
    for (int g = 0; g < 8; g++) { sum8[g] = 0.f; sq8[g] = 0.f; }

    float* hrow = d_h1 + (size_t)b * C1 * MPOS + m;
#pragma unroll
    for (int c = 0; c < C1; c++) {
        const float* wr = ws + c * 6;
        float o = bs[c];
        o = fmaf(wr[0], f0, o); o = fmaf(wr[1], f1, o); o = fmaf(wr[2], f2, o);
        o = fmaf(wr[3], f3, o); o = fmaf(wr[4], f4, o); o = fmaf(wr[5], f5, o);
        hrow[(size_t)c * MPOS] = o;
        sum8[c / 12] += o;
        sq8[c / 12]  += o * o;
    }

    // warp reduce 16 quantities
#pragma unroll
    for (int g = 0; g < 8; g++) {
        for (int off = 16; off; off >>= 1) {
            sum8[g] += __shfl_down_sync(0xffffffffu, sum8[g], off);
            sq8[g]  += __shfl_down_sync(0xffffffffu, sq8[g], off);
        }
    }
    int wid = tid >> 5, lane = tid & 31;
    if (lane == 0) {
#pragma unroll
        for (int g = 0; g < 8; g++) {
            red[wid][g * 2 + 0] = sum8[g];
            red[wid][g * 2 + 1] = sq8[g];
        }
    }
    __syncthreads();
    if (tid < 16) {
        float acc = 0.f;
#pragma unroll
        for (int w = 0; w < 8; w++) acc += red[w][tid];
        int g = tid >> 1, which = tid & 1;
        int bb = (blockIdx.x * 256) / MPOS;  // whole block shares one batch
        atomicAdd(&stats0[((size_t)(bb * GRP + g)) * 2 + which], (double)acc);
    }
}

// ---------------------------------------------------------------------------
// Finalize GN stats: mean/rstd per (b,g) for one stage.
// ---------------------------------------------------------------------------
__global__ void finalize_kernel(int stage, double cnt) {
    int t = threadIdx.x;
    if (t >= BATCH * GRP) return;
    const double* sp = d_stats + (size_t)stage * BATCH * GRP * 2 + t * 2;
    double mean = sp[0] / cnt;
    double var  = sp[1] / cnt - mean * mean;
    if (var < 0.0) var = 0.0;
    double rstd = 1.0 / sqrt(var + 1e-5);
    float* mp = d_mr + (size_t)stage * BATCH * GRP * 2 + t * 2;
    mp[0] = (float)mean;
    mp[1] = (float)rstd;
}

// ---------------------------------------------------------------------------
// Generic conv1x1 GEMM: 96 out-channel x 128 position tile, 256 threads,
// 6x8 register tiles. Optional on-the-fly GN+ReLU on the input, optional
// GN-stats accumulation on the raw output. K chunked by 96.
// ---------------------------------------------------------------------------
__global__ void __launch_bounds__(256, 2)
mlp_gemm(const float* __restrict__ in,      // [B][CIN][Mtot]
         const float* __restrict__ w,       // [COUTtot][CIN]
         const float* __restrict__ bias,    // [COUTtot]
         float* __restrict__ outbuf,        // [B][COUTtot][Mtot]
         int CIN, int COUTtot, int Mtot,
         const float* __restrict__ gamma,   // input GN affine (or null)
         const float* __restrict__ beta,
         const float* __restrict__ mr_in,   // [B][G][2] mean/rstd (or null)
         int in_cpg,
         double* __restrict__ stats_out,    // [B][G][2] (or null)
         int out_cpg) {
    extern __shared__ float smem[];
    float* xs  = smem;              // 96 x 128
    float* wsT = smem + 96 * 128;   // 96 x 97 (padded)
    float* sc  = wsT + 96 * 97;     // up to 192
    float* shf = sc + 192;          // up to 192

    int b = blockIdx.y;
    int m0 = blockIdx.x * 128;
    int co0 = blockIdx.z * 96;
    int tid = threadIdx.x;
    int tc = tid >> 4;   // 0..15 -> 6 channels each
    int tp = tid & 15;   // 0..15 -> 8 positions each

    if (gamma) {
        for (int k = tid; k < CIN; k += 256) {
            int g = k / in_cpg;
            float mean = mr_in[(b * GRP + g) * 2 + 0];
            float rstd = mr_in[(b * GRP + g) * 2 + 1];
            float s = rstd * gamma[k];
            sc[k]  = s;
            shf[k] = beta[k] - mean * s;
        }
    }
    __syncthreads();

    float acc[6][8];
#pragma unroll
    for (int ci = 0; ci < 6; ci++)
#pragma unroll
        for (int pi = 0; pi < 8; pi++) acc[ci][pi] = 0.f;

    for (int kc = 0; kc < CIN; kc += 96) {
        // stage weights (transposed, padded)
        for (int i = tid; i < 96 * 96; i += 256) {
            int c = i / 96, kk = i % 96;
            wsT[kk * 97 + c] = w[(size_t)(co0 + c) * CIN + kc + kk];
        }
        // stage input tile (vectorized), with optional GN+ReLU
        const float* inb = in + ((size_t)b * CIN + kc) * Mtot + m0;
        for (int i = tid; i < 96 * 32; i += 256) {
            int kk = i >> 5, p4 = i & 31;
            float4 v = ((const float4*)(inb + (size_t)kk * Mtot))[p4];
            if (gamma) {
                int k = kc + kk;
                float s = sc[k], h = shf[k];
                v.x = fmaxf(fmaf(v.x, s, h), 0.f);
                v.y = fmaxf(fmaf(v.y, s, h), 0.f);
                v.z = fmaxf(fmaf(v.z, s, h), 0.f);
                v.w = fmaxf(fmaf(v.w, s, h), 0.f);
            }
            ((float4*)(xs + kk * 128))[p4] = v;
        }
        __syncthreads();

#pragma unroll 8
        for (int kk = 0; kk < 96; kk++) {
            float4 xa = *(const float4*)&xs[kk * 128 + tp * 8];
            float4 xb = *(const float4*)&xs[kk * 128 + tp * 8 + 4];
            float wr[6];
#pragma unroll
            for (int ci = 0; ci < 6; ci++) wr[ci] = wsT[kk * 97 + tc * 6 + ci];
#pragma unroll
            for (int ci = 0; ci < 6; ci++) {
                acc[ci][0] = fmaf(wr[ci], xa.x, acc[ci][0]);
                acc[ci][1] = fmaf(wr[ci], xa.y, acc[ci][1]);
                acc[ci][2] = fmaf(wr[ci], xa.z, acc[ci][2]);
                acc[ci][3] = fmaf(wr[ci], xa.w, acc[ci][3]);
                acc[ci][4] = fmaf(wr[ci], xb.x, acc[ci][4]);
                acc[ci][5] = fmaf(wr[ci], xb.y, acc[ci][5]);
                acc[ci][6] = fmaf(wr[ci], xb.z, acc[ci][6]);
                acc[ci][7] = fmaf(wr[ci], xb.w, acc[ci][7]);
            }
        }
        __syncthreads();
    }

    // epilogue: add bias, store raw, accumulate stats
    int cbase = co0 + tc * 6;
    float gsum = 0.f, gsq = 0.f;
#pragma unroll
    for (int ci = 0; ci < 6; ci++) {
        float bv = bias[cbase + ci];
        float v0 = acc[ci][0] + bv, v1 = acc[ci][1] + bv, v2 = acc[ci][2] + bv, v3 = acc[ci][3] + bv;
        float v4 = acc[ci][4] + bv, v5 = acc[ci][5] + bv, v6 = acc[ci][6] + bv, v7 = acc[ci][7] + bv;
        float* orow = outbuf + ((size_t)b * COUTtot + cbase + ci) * Mtot + m0 + tp * 8;
        ((float4*)orow)[0] = make_float4(v0, v1, v2, v3);
        ((float4*)orow)[1] = make_float4(v4, v5, v6, v7);
        if (stats_out) {
            gsum += v0 + v1 + v2 + v3 + v4 + v5 + v6 + v7;
            gsq  += v0 * v0 + v1 * v1 + v2 * v2 + v3 * v3 + v4 * v4 + v5 * v5 + v6 * v6 + v7 * v7;
        }
    }
    if (stats_out) {
        // each warp spans exactly 12 consecutive channels -> single group
        for (int off = 16; off; off >>= 1) {
            gsum += __shfl_down_sync(0xffffffffu, gsum, off);
            gsq  += __shfl_down_sync(0xffffffffu, gsq, off);
        }
        if ((tid & 31) == 0) {
            int g = cbase / out_cpg;
            atomicAdd(&stats_out[((size_t)(b * GRP + g)) * 2 + 0], (double)gsum);
            atomicAdd(&stats_out[((size_t)(b * GRP + g)) * 2 + 1], (double)gsq);
        }
    }
}

// ---------------------------------------------------------------------------
// Max pool over samples, with stage-2 GN+ReLU applied elementwise first.
// ---------------------------------------------------------------------------
__global__ void pool_kernel(const float* __restrict__ gamma,
                            const float* __restrict__ beta,
                            const float* __restrict__ mr) {
    int q = blockIdx.x * 256 + threadIdx.x;   // < BATCH*C3*NPTS
    int b = q / (C3 * NPTS);
    int r = q % (C3 * NPTS);
    int c = r / NPTS;
    int n = r % NPTS;
    int g = c / 24;
    float mean = mr[(b * GRP + g) * 2 + 0];
    float rstd = mr[(b * GRP + g) * 2 + 1];
    float s = rstd * gamma[c];
    float h = beta[c] - mean * s;
    const float* row = d_h3 + ((size_t)b * C3 + c) * MPOS + n;
    float mx = 0.f;  // relu output is >= 0
#pragma unroll
    for (int ss = 0; ss < NS; ss++) {
        float v = fmaxf(fmaf(row[(size_t)ss * NPTS], s, h), 0.f);
        mx = fmaxf(mx, v);
    }
    d_pool[((size_t)b * C3 + c) * NPTS + n] = mx;
}

// ---------------------------------------------------------------------------
// Final stage: GN(stage4)+ReLU on p2, conv 96->96 (+bias), transpose to
// [b][n][c] and L2-normalize per point.
// ---------------------------------------------------------------------------
__global__ void __launch_bounds__(256, 2)
final_kernel(const float* __restrict__ in,     // [B][96][2048]
             const float* __restrict__ w,      // [96][96]
             const float* __restrict__ bias,   // [96]
             const float* __restrict__ gamma,
             const float* __restrict__ beta,
             const float* __restrict__ mr,     // stage-4 mean/rstd
             float* __restrict__ out) {        // [B][N][96]
    extern __shared__ float smem[];
    float* xs  = smem;
    float* wsT = smem + 96 * 128;
    float* sc  = wsT + 96 * 97;
    float* shf = sc + 192;

    int b = blockIdx.y;
    int m0 = blockIdx.x * 128;
    int tid = threadIdx.x;
    int tc = tid >> 4, tp = tid & 15;

    for (int k = tid; k < 96; k += 256) {
        int g = k / 12;
        float mean = mr[(b * GRP + g) * 2 + 0];
        float rstd = mr[(b * GRP + g) * 2 + 1];
        float s = rstd * gamma[k];
        sc[k]  = s;
        shf[k] = beta[k] - mean * s;
    }
    __syncthreads();

    for (int i = tid; i < 96 * 96; i += 256) {
        int c = i / 96, kk = i % 96;
        wsT[kk * 97 + c] = w[(size_t)c * 96 + kk];
    }
    const float* inb = in + (size_t)b * 96 * NPTS + m0;
    for (int i = tid; i < 96 * 32; i += 256) {
        int kk = i >> 5, p4 = i & 31;
        float4 v = ((const float4*)(inb + (size_t)kk * NPTS))[p4];
        float s = sc[kk], h = shf[kk];
        v.x = fmaxf(fmaf(v.x, s, h), 0.f);
        v.y = fmaxf(fmaf(v.y, s, h), 0.f);
        v.z = fmaxf(fmaf(v.z, s, h), 0.f);
        v.w = fmaxf(fmaf(v.w, s, h), 0.f);
        ((float4*)(xs + kk * 128))[p4] = v;
    }
    __syncthreads();

    float acc[6][8];
#pragma unroll
    for (int ci = 0; ci < 6; ci++)
#pragma unroll
        for (int pi = 0; pi < 8; pi++) acc[ci][pi] = 0.f;

#pragma unroll 8
    for (int kk = 0; kk < 96; kk++) {
        float4 xa = *(const float4*)&xs[kk * 128 + tp * 8];
        float4 xb = *(const float4*)&xs[kk * 128 + tp * 8 + 4];
        float wr[6];
#pragma unroll
        for (int ci = 0; ci < 6; ci++) wr[ci] = wsT[kk * 97 + tc * 6 + ci];
#pragma unroll
        for (int ci = 0; ci < 6; ci++) {
            acc[ci][0] = fmaf(wr[ci], xa.x, acc[ci][0]);
            acc[ci][1] = fmaf(wr[ci], xa.y, acc[ci][1]);
            acc[ci][2] = fmaf(wr[ci], xa.z, acc[ci][2]);
            acc[ci][3] = fmaf(wr[ci], xa.w, acc[ci][3]);
            acc[ci][4] = fmaf(wr[ci], xb.x, acc[ci][4]);
            acc[ci][5] = fmaf(wr[ci], xb.y, acc[ci][5]);
            acc[ci][6] = fmaf(wr[ci], xb.z, acc[ci][6]);
            acc[ci][7] = fmaf(wr[ci], xb.w, acc[ci][7]);
        }
    }
    __syncthreads();

    // stash outputs (bias added) into shared [96][129]
    float* ob = smem;
#pragma unroll
    for (int ci = 0; ci < 6; ci++) {
        float bv = bias[tc * 6 + ci];
#pragma unroll
        for (int pi = 0; pi < 8; pi++)
            ob[(tc * 6 + ci) * 129 + tp * 8 + pi] = acc[ci][pi] + bv;
    }
    __syncthreads();

    if (tid < 128) {
        int p = tid;
        float s2 = 0.f;
#pragma unroll
        for (int c = 0; c < 96; c++) {
            float v = ob[c * 129 + p];
            s2 += v * v;
        }
        float rinv = rsqrtf(s2);
        float* op = out + ((size_t)b * NPTS + m0 + p) * 96;
#pragma unroll
        for (int c = 0; c < 96; c++) op[c] = ob[c * 129 + p] * rinv;
    }
}

// ---------------------------------------------------------------------------
// Launch
// ---------------------------------------------------------------------------
extern "C" void kernel_launch(void* const* d_in, const int* in_sizes, int n_in,
                              void* d_out, int out_size) {
    const float* xyz     = (const float*)d_in[0];
    const float* pre_w1  = (const float*)d_in[1];
    const float* pre_b1  = (const float*)d_in[2];
    const float* pre_g1  = (const float*)d_in[3];
    const float* pre_be1 = (const float*)d_in[4];
    const float* pre_w2  = (const float*)d_in[5];
    const float* pre_b2  = (const float*)d_in[6];
    const float* pre_g2  = (const float*)d_in[7];
    const float* pre_be2 = (const float*)d_in[8];
    const float* pre_w3  = (const float*)d_in[9];
    const float* pre_b3  = (const float*)d_in[10];
    const float* pre_g3  = (const float*)d_in[11];
    const float* pre_be3 = (const float*)d_in[12];
    const float* post_w1 = (const float*)d_in[13];
    const float* post_b1 = (const float*)d_in[14];
    const float* post_g1 = (const float*)d_in[15];
    const float* post_be1= (const float*)d_in[16];
    const float* post_w2 = (const float*)d_in[17];
    const float* post_b2 = (const float*)d_in[18];
    const float* post_g2 = (const float*)d_in[19];
    const float* post_be2= (const float*)d_in[20];
    const float* post_w3 = (const float*)d_in[21];
    const float* post_b3 = (const float*)d_in[22];
    float* out = (float*)d_out;

    double* statsP; float* mrP;
    float *h1P, *h2P, *h3P, *poolP, *p1P, *p2P;
    cudaGetSymbolAddress((void**)&statsP, d_stats);
    cudaGetSymbolAddress((void**)&mrP,    d_mr);
    cudaGetSymbolAddress((void**)&h1P,    d_h1);
    cudaGetSymbolAddress((void**)&h2P,    d_h2);
    cudaGetSymbolAddress((void**)&h3P,    d_h3);
    cudaGetSymbolAddress((void**)&poolP,  d_pool);
    cudaGetSymbolAddress((void**)&p1P,    d_p1);
    cudaGetSymbolAddress((void**)&p2P,    d_p2);

    const int SMEM = (96 * 128 + 96 * 97 + 2 * 192) * (int)sizeof(float); // 87936
    cudaFuncSetAttribute(mlp_gemm,     cudaFuncAttributeMaxDynamicSharedMemorySize, SMEM);
    cudaFuncSetAttribute(final_kernel, cudaFuncAttributeMaxDynamicSharedMemorySize, SMEM);

    const int SOFF = BATCH * GRP * 2;  // per-stage stride

    zero_stats_kernel<<<1, 256>>>();
    ballquery_kernel<<<512, 256>>>(xyz);
    conv1_kernel<<<(BATCH * MPOS) / 256, 256>>>(xyz, pre_w1, pre_b1, statsP + 0 * SOFF);
    finalize_kernel<<<1, 32>>>(0, 12.0 * MPOS);

    // conv2: 96 -> 96, input GN(stage0), stats -> stage1
    mlp_gemm<<<dim3(MPOS / 128, BATCH, 1), 256, SMEM>>>(
        h1P, pre_w2, pre_b2, h2P, 96, 96, MPOS,
        pre_g1, pre_be1, mrP + 0 * SOFF, 12, statsP + 1 * SOFF, 12);
    finalize_kernel<<<1, 32>>>(1, 12.0 * MPOS);

    // conv3: 96 -> 192, input GN(stage1), stats -> stage2
    mlp_gemm<<<dim3(MPOS / 128, BATCH, 2), 256, SMEM>>>(
        h2P, pre_w3, pre_b3, h3P, 96, 192, MPOS,
        pre_g2, pre_be2, mrP + 1 * SOFF, 12, statsP + 2 * SOFF, 24);
    finalize_kernel<<<1, 32>>>(2, 24.0 * MPOS);

    // GN(stage2)+ReLU then max-pool over samples
    pool_kernel<<<(BATCH * C3 * NPTS) / 256, 256>>>(pre_g3, pre_be3, mrP + 2 * SOFF);

    // post1: 192 -> 192, no input GN, stats -> stage3
    mlp_gemm<<<dim3(NPTS / 128, BATCH, 2), 256, SMEM>>>(
        poolP, post_w1, post_b1, p1P, 192, 192, NPTS,
        (const float*)0, (const float*)0, (const float*)0, 0, statsP + 3 * SOFF, 24);
    finalize_kernel<<<1, 32>>>(3, 24.0 * NPTS);

    // post2: 192 -> 96, input GN(stage3), stats -> stage4
    mlp_gemm<<<dim3(NPTS / 128, BATCH, 1), 256, SMEM>>>(
        p1P, post_w2, post_b2, p2P, 192, 96, NPTS,
        post_g1, post_be1, mrP + 3 * SOFF, 24, statsP + 4 * SOFF, 12);
    finalize_kernel<<<1, 32>>>(4, 12.0 * NPTS);

    // final: GN(stage4)+ReLU, conv 96->96 + bias, transpose + L2 normalize
    final_kernel<<<dim3(NPTS / 128, BATCH, 1), 256, SMEM>>>(
        p2P, post_w3, post_b3, post_g2, post_be2, mrP + 4 * SOFF, out);
}

// round 5
// speedup vs baseline: 1.4193x; 1.4193x over previous
#include <cuda_runtime.h>
#include <cuda_bf16.h>
#include <math.h>
#include <stdint.h>

#define BATCH 2
#define NPTS  2048
#define NS    64
#define MPOS  (NS * NPTS)   // 131072 positions per batch
#define C1    96
#define C3    192
#define GRP   8
#define R2    0.09f
#define SAB   208           // bf16 row stride in bytes (104 elements)

// ---------------------------------------------------------------------------
// Static device scratch
// ---------------------------------------------------------------------------
__device__ __align__(256) int    d_idx[BATCH * NS * NPTS];
__device__ __align__(256) float  d_h2[(size_t)BATCH * C1 * MPOS];      // raw conv2 out [b][c][m]
__device__ __align__(256) float  d_poolpart[2 * BATCH * C3 * NPTS];    // per-schunk raw max
__device__ __align__(256) float  d_pool[(size_t)BATCH * C3 * NPTS];    // pooled post GN+relu
__device__ __align__(256) float  d_p1[(size_t)BATCH * C3 * NPTS];
__device__ __align__(256) float  d_p2[(size_t)BATCH * C1 * NPTS];
__device__ __align__(256) double d_stats[5 * BATCH * GRP * 2];
__device__ __align__(256) float  d_mr[5 * BATCH * GRP * 2];

// ---------------------------------------------------------------------------
// Helpers
// ---------------------------------------------------------------------------
__device__ __forceinline__ uint32_t s2u(const void* p) {
    uint32_t a;
    asm("{ .reg .u64 t; cvta.to.shared.u64 t, %1; cvt.u32.u64 %0, t; }" : "=r"(a) : "l"(p));
    return a;
}
__device__ __forceinline__ void ldmat4(uint32_t* r, uint32_t addr) {
    asm volatile("ldmatrix.sync.aligned.m8n8.x4.shared.b16 {%0,%1,%2,%3}, [%4];"
                 : "=r"(r[0]), "=r"(r[1]), "=r"(r[2]), "=r"(r[3]) : "r"(addr));
}
__device__ __forceinline__ void mma16816(float* c, const uint32_t* a, const uint32_t* b) {
    asm volatile("mma.sync.aligned.m16n8k16.row.col.f32.bf16.bf16.f32 "
                 "{%0,%1,%2,%3}, {%4,%5,%6,%7}, {%8,%9}, {%0,%1,%2,%3};"
                 : "+f"(c[0]), "+f"(c[1]), "+f"(c[2]), "+f"(c[3])
                 : "r"(a[0]), "r"(a[1]), "r"(a[2]), "r"(a[3]), "r"(b[0]), "r"(b[1]));
}
__device__ __forceinline__ void split2(float x0, float x1, uint32_t* hi, uint32_t* lo) {
    __nv_bfloat16 h0 = __float2bfloat16_rn(x0);
    __nv_bfloat16 h1 = __float2bfloat16_rn(x1);
    float r0 = x0 - __bfloat162float(h0);
    float r1 = x1 - __bfloat162float(h1);
    __nv_bfloat16 l0 = __float2bfloat16_rn(r0);
    __nv_bfloat16 l1 = __float2bfloat16_rn(r1);
    *hi = (uint32_t)__bfloat16_as_ushort(h0) | ((uint32_t)__bfloat16_as_ushort(h1) << 16);
    *lo = (uint32_t)__bfloat16_as_ushort(l0) | ((uint32_t)__bfloat16_as_ushort(l1) << 16);
}

// ---------------------------------------------------------------------------
// Init: zero stats
// ---------------------------------------------------------------------------
__global__ void init_kernel() {
    int t = threadIdx.x;
    if (t < 5 * BATCH * GRP * 2) d_stats[t] = 0.0;
}

// ---------------------------------------------------------------------------
// Ball query (known-good from R2)
// ---------------------------------------------------------------------------
__global__ void ballquery_kernel(const float* __restrict__ xyz) {
    int warp = (blockIdx.x * blockDim.x + threadIdx.x) >> 5;
    int lane = threadIdx.x & 31;
    if (warp >= BATCH * NPTS) return;
    int b = warp / NPTS, i = warp % NPTS;
    const float* base = xyz + (size_t)b * NPTS * 3;
    float cx = base[i * 3 + 0], cy = base[i * 3 + 1], cz = base[i * 3 + 2];
    int count = 0, first = 0;
    for (int jb = 0; jb < NPTS; jb += 32) {
        int j = jb + lane;
        float dx = base[j * 3 + 0] - cx;
        float dy = base[j * 3 + 1] - cy;
        float dz = base[j * 3 + 2] - cz;
        float d2 = dx * dx + dy * dy + dz * dz;
        bool ok = (d2 <= R2);
        unsigned mask = __ballot_sync(0xffffffffu, ok);
        if (ok) {
            int pos = count + __popc(mask & ((1u << lane) - 1u));
            if (pos < NS) d_idx[((size_t)(b * NS + pos)) * NPTS + i] = j;
        }
        if (count == 0 && mask) first = jb + __ffs(mask) - 1;
        count += __popc(mask);
        if (count >= NS) break;
    }
    for (int p = count + lane; p < NS; p += 32)
        d_idx[((size_t)(b * NS + p)) * NPTS + i] = first;
}

// ---------------------------------------------------------------------------
// Conv1 stats-only pass (stage-0 GN stats; no h1 store)
// ---------------------------------------------------------------------------
__global__ void conv1_stats_kernel(const float* __restrict__ xyz,
                                   const float* __restrict__ w1,
                                   const float* __restrict__ b1,
                                   double* __restrict__ stats0) {
    __shared__ float ws[C1 * 6];
    __shared__ float bs[C1];
    __shared__ float red[8][16];
    int tid = threadIdx.x;
    for (int i = tid; i < C1 * 6; i += 256) ws[i] = w1[i];
    if (tid < C1) bs[tid] = b1[tid];
    __syncthreads();

    int q = blockIdx.x * 256 + tid;
    int b = q / MPOS, m = q % MPOS;
    int s = m / NPTS, n = m % NPTS;
    int j = d_idx[((size_t)(b * NS + s)) * NPTS + n];
    const float* xb = xyz + (size_t)b * NPTS * 3;
    float f0 = xb[n * 3 + 0], f1 = xb[n * 3 + 1], f2 = xb[n * 3 + 2];
    float f3 = xb[j * 3 + 0] - f0, f4 = xb[j * 3 + 1] - f1, f5 = xb[j * 3 + 2] - f2;

    float sum8[8], sq8[8];
#pragma unroll
    for (int g = 0; g < 8; g++) { sum8[g] = 0.f; sq8[g] = 0.f; }
#pragma unroll
    for (int c = 0; c < C1; c++) {
        const float* wr = ws + c * 6;
        float o = bs[c];
        o = fmaf(wr[0], f0, o); o = fmaf(wr[1], f1, o); o = fmaf(wr[2], f2, o);
        o = fmaf(wr[3], f3, o); o = fmaf(wr[4], f4, o); o = fmaf(wr[5], f5, o);
        sum8[c / 12] += o;
        sq8[c / 12]  += o * o;
    }
#pragma unroll
    for (int g = 0; g < 8; g++) {
        for (int off = 16; off; off >>= 1) {
            sum8[g] += __shfl_down_sync(0xffffffffu, sum8[g], off);
            sq8[g]  += __shfl_down_sync(0xffffffffu, sq8[g], off);
        }
    }
    int wid = tid >> 5, lane = tid & 31;
    if (lane == 0) {
#pragma unroll
        for (int g = 0; g < 8; g++) {
            red[wid][g * 2 + 0] = sum8[g];
            red[wid][g * 2 + 1] = sq8[g];
        }
    }
    __syncthreads();
    if (tid < 16) {
        float acc = 0.f;
#pragma unroll
        for (int w = 0; w < 8; w++) acc += red[w][tid];
        int g = tid >> 1, which = tid & 1;
        int bb = (blockIdx.x * 256) / MPOS;
        atomicAdd(&stats0[((size_t)(bb * GRP + g)) * 2 + which], (double)acc);
    }
}

__global__ void finalize_kernel(int stage, double cnt) {
    int t = threadIdx.x;
    if (t >= BATCH * GRP) return;
    const double* sp = d_stats + (size_t)stage * BATCH * GRP * 2 + t * 2;
    double mean = sp[0] / cnt;
    double var  = sp[1] / cnt - mean * mean;
    if (var < 0.0) var = 0.0;
    double rstd = 1.0 / sqrt(var + 1e-5);
    float* mp = d_mr + (size_t)stage * BATCH * GRP * 2 + t * 2;
    mp[0] = (float)mean;
    mp[1] = (float)rstd;
}

// ---------------------------------------------------------------------------
// conv2 via mma.sync: tile = 128 positions x 96 channels, K=96, bf16 hi/lo x3.
// Producer recomputes conv1 from xyz+idx, applies GN0+ReLU, splits to bf16.
// SMEM: A_hi[128x104bf16]@0, A_lo@26624, W_hi[96x104]@53248, W_lo@73216,
//       misc@93184. Epilogue stage [96][132] f32 overlaps A region.
// ---------------------------------------------------------------------------
#define C2_ALO 26624
#define C2_WHI 53248
#define C2_WLO 73216
#define C2_MSC 93184
#define C2_SMEM 100352

__global__ void __launch_bounds__(256, 1)
conv2_mma(const float* __restrict__ xyz,
          const float* __restrict__ w1, const float* __restrict__ b1,
          const float* __restrict__ w2, const float* __restrict__ b2,
          const float* __restrict__ gamma, const float* __restrict__ beta,
          const float* __restrict__ mr0, double* __restrict__ stats1,
          float* __restrict__ h2) {
    extern __shared__ char sm[];
    uint32_t sb = s2u(sm);
    float* stage = (float*)sm;                 // 96 x 132 f32 (overlaps A)
    float* sc    = (float*)(sm + C2_MSC);      // 96
    float* shf   = sc + 96;
    float* biasS = shf + 96;                   // 96
    float* w1s   = biasS + 96;                 // 576
    float* b1s   = w1s + 576;                  // 96
    float* feat  = b1s + 96;                   // 128*6

    int tid = threadIdx.x, w = tid >> 5, l = tid & 31;
    int b = blockIdx.y;
    int mw = w & 3, nw = w >> 2;               // warp: 32 pos x 48 ch

    for (int k = tid; k < 96; k += 256) {
        int g = k / 12;
        float mean = mr0[(b * GRP + g) * 2 + 0];
        float rstd = mr0[(b * GRP + g) * 2 + 1];
        float s = rstd * gamma[k];
        sc[k]  = s;
        shf[k] = beta[k] - mean * s;
    }
    if (tid < 96) biasS[tid] = b2[tid];
    for (int i = tid; i < 576; i += 256) w1s[i] = w1[i];
    if (tid < 96) b1s[tid] = b1[tid];
    // weights: bf16 hi/lo split, row stride 208B
    for (int e = tid; e < 96 * 48; e += 256) {
        int kp = e % 48, c = e / 48;
        float2 v = *(const float2*)(w2 + (size_t)c * 96 + 2 * kp);
        uint32_t hw, lw;
        split2(v.x, v.y, &hw, &lw);
        *(uint32_t*)(sm + C2_WHI + c * SAB + kp * 4) = hw;
        *(uint32_t*)(sm + C2_WLO + c * SAB + kp * 4) = lw;
    }
    __syncthreads();

    float gsum[4] = {0, 0, 0, 0}, gsq[4] = {0, 0, 0, 0};
    int pos_t = tid & 127, chalf = tid >> 7;

    for (int t = blockIdx.x; t < 1024; t += gridDim.x) {
        int m0 = t * 128;
        // producer: conv1 -> GN0+ReLU -> bf16 split
        if (tid < 128) {
            int s_ = m0 >> 11, n = (m0 & 2047) + tid;
            int j = d_idx[((size_t)(b * NS + s_)) * NPTS + n];
            const float* xb = xyz + (size_t)b * NPTS * 3;
            float f0 = xb[n * 3 + 0], f1 = xb[n * 3 + 1], f2 = xb[n * 3 + 2];
            feat[tid * 6 + 0] = f0;
            feat[tid * 6 + 1] = f1;
            feat[tid * 6 + 2] = f2;
            feat[tid * 6 + 3] = xb[j * 3 + 0] - f0;
            feat[tid * 6 + 4] = xb[j * 3 + 1] - f1;
            feat[tid * 6 + 5] = xb[j * 3 + 2] - f2;
        }
        __syncthreads();
        for (int e = tid; e < 6144; e += 256) {
            int kp = e % 48, pos = e / 48;
            int k0 = 2 * kp, k1 = k0 + 1;
            const float* fr = feat + pos * 6;
            float o0 = b1s[k0], o1 = b1s[k1];
            const float* wr0 = w1s + k0 * 6;
            const float* wr1 = w1s + k1 * 6;
#pragma unroll
            for (int j2 = 0; j2 < 6; j2++) {
                float fv = fr[j2];
                o0 = fmaf(wr0[j2], fv, o0);
                o1 = fmaf(wr1[j2], fv, o1);
            }
            o0 = fmaxf(fmaf(o0, sc[k0], shf[k0]), 0.f);
            o1 = fmaxf(fmaf(o1, sc[k1], shf[k1]), 0.f);
            uint32_t hw, lw;
            split2(o0, o1, &hw, &lw);
            *(uint32_t*)(sm + pos * SAB + kp * 4) = hw;
            *(uint32_t*)(sm + C2_ALO + pos * SAB + kp * 4) = lw;
        }
        __syncthreads();

        // mma: C[2 m16][6 n8]
        float acc[2][6][4];
#pragma unroll
        for (int mi = 0; mi < 2; mi++)
#pragma unroll
            for (int nj = 0; nj < 6; nj++)
#pragma unroll
                for (int r = 0; r < 4; r++) acc[mi][nj][r] = 0.f;

        int arow = l & 15;
        int ahk  = (l >> 4) << 3;
        int bc   = (l & 7) + ((l >> 4) << 3);
        int bhk  = ((l >> 3) & 1) << 3;
#pragma unroll 1
        for (int ks = 0; ks < 6; ks++) {
            int k0 = ks * 16;
            uint32_t ah[2][4], al[2][4], bh[6][2], bl[6][2];
#pragma unroll
            for (int mi = 0; mi < 2; mi++) {
                uint32_t ad = sb + (mw * 32 + mi * 16 + arow) * SAB + (k0 + ahk) * 2;
                ldmat4(ah[mi], ad);
                ldmat4(al[mi], ad + C2_ALO);
            }
#pragma unroll
            for (int np = 0; np < 3; np++) {
                uint32_t bd = sb + C2_WHI + (nw * 48 + np * 16 + bc) * SAB + (k0 + bhk) * 2;
                uint32_t r4[4];
                ldmat4(r4, bd);
                bh[2 * np][0] = r4[0]; bh[2 * np][1] = r4[1];
                bh[2 * np + 1][0] = r4[2]; bh[2 * np + 1][1] = r4[3];
                ldmat4(r4, bd + (C2_WLO - C2_WHI));
                bl[2 * np][0] = r4[0]; bl[2 * np][1] = r4[1];
                bl[2 * np + 1][0] = r4[2]; bl[2 * np + 1][1] = r4[3];
            }
#pragma unroll
            for (int mi = 0; mi < 2; mi++)
#pragma unroll
                for (int nj = 0; nj < 6; nj++) {
                    mma16816(acc[mi][nj], ah[mi], bh[nj]);
                    mma16816(acc[mi][nj], al[mi], bh[nj]);
                    mma16816(acc[mi][nj], ah[mi], bl[nj]);
                }
        }
        __syncthreads();   // A reads done; stage may overwrite

        int g2 = l >> 2, t4 = l & 3;
#pragma unroll
        for (int mi = 0; mi < 2; mi++)
#pragma unroll
            for (int nj = 0; nj < 6; nj++) {
                int row = mw * 32 + mi * 16 + g2;
                int col = nw * 48 + nj * 8 + t4 * 2;
                float bv0 = biasS[col], bv1 = biasS[col + 1];
                stage[col * 132 + row]           = acc[mi][nj][0] + bv0;
                stage[(col + 1) * 132 + row]     = acc[mi][nj][1] + bv1;
                stage[col * 132 + row + 8]       = acc[mi][nj][2] + bv0;
                stage[(col + 1) * 132 + row + 8] = acc[mi][nj][3] + bv1;
            }
        __syncthreads();

        // raw h2 write (coalesced float4)
        for (int e = tid; e < 3072; e += 256) {
            int c = e >> 5, pq = e & 31;
            float4 v = *(float4*)(stage + c * 132 + pq * 4);
            *(float4*)(h2 + ((size_t)b * 96 + c) * MPOS + m0 + pq * 4) = v;
        }
        // stage-1 stats: thread owns (pos, 48 contiguous channels)
        {
            int c0 = chalf * 48;
#pragma unroll
            for (int k = 0; k < 48; k++) {
                float v = stage[(c0 + k) * 132 + pos_t];
                gsum[k / 12] += v;
                gsq[k / 12]  += v * v;
            }
        }
        __syncthreads();   // readers done before next producer
    }

    // reduce stats (chalf constant within warp)
#pragma unroll
    for (int g = 0; g < 4; g++) {
        for (int off = 16; off; off >>= 1) {
            gsum[g] += __shfl_down_sync(0xffffffffu, gsum[g], off);
            gsq[g]  += __shfl_down_sync(0xffffffffu, gsq[g], off);
        }
    }
    if (l == 0) {
        int gb = chalf * 4;
#pragma unroll
        for (int g = 0; g < 4; g++) {
            atomicAdd(&stats1[((size_t)(b * GRP + gb + g)) * 2 + 0], (double)gsum[g]);
            atomicAdd(&stats1[((size_t)(b * GRP + gb + g)) * 2 + 1], (double)gsq[g]);
        }
    }
}

// ---------------------------------------------------------------------------
// conv3 via mma.sync: tile = 64 positions x 192 channels, looped over 32
// s-samples per block; pooled max kept in 48 regs/thread (atomic-free).
// grid = (32 n-chunks, 2 batches, 2 s-chunks).
// SMEM: A_hi[64x104]@0, A_lo@13312, W_hi[192x104]@26624, W_lo@66560,
//       stage[192][68] f32 @106496, misc@158720.
// ---------------------------------------------------------------------------
#define C3_ALO 13312
#define C3_WHI 26624
#define C3_WLO 66560
#define C3_STG 106496
#define C3_MSC 158720
#define C3_SMEM 160256

__global__ void __launch_bounds__(256, 1)
conv3_mma(const float* __restrict__ h2,
          const float* __restrict__ w3, const float* __restrict__ b3,
          const float* __restrict__ gamma, const float* __restrict__ beta,
          const float* __restrict__ mr1, double* __restrict__ stats2,
          float* __restrict__ poolpart) {
    extern __shared__ char sm[];
    uint32_t sb = s2u(sm);
    float* stage = (float*)(sm + C3_STG);      // 192 x 68 f32
    float* sc    = (float*)(sm + C3_MSC);      // 96
    float* shf   = sc + 96;
    float* biasS = shf + 96;                   // 192

    int tid = threadIdx.x, w = tid >> 5, l = tid & 31;
    int nc = blockIdx.x, b = blockIdx.y, schunk = blockIdx.z;
    int mw = w & 1, nw = w >> 1;               // warp: 32 pos x 48 ch

    for (int k = tid; k < 96; k += 256) {
        int g = k / 12;
        float mean = mr1[(b * GRP + g) * 2 + 0];
        float rstd = mr1[(b * GRP + g) * 2 + 1];
        float s = rstd * gamma[k];
        sc[k]  = s;
        shf[k] = beta[k] - mean * s;
    }
    if (tid < 192) biasS[tid] = b3[tid];
    for (int e = tid; e < 192 * 48; e += 256) {
        int kp = e % 48, c = e / 48;
        float2 v = *(const float2*)(w3 + (size_t)c * 96 + 2 * kp);
        uint32_t hw, lw;
        split2(v.x, v.y, &hw, &lw);
        *(uint32_t*)(sm + C3_WHI + c * SAB + kp * 4) = hw;
        *(uint32_t*)(sm + C3_WLO + c * SAB + kp * 4) = lw;
    }
    __syncthreads();

    int pos_t = tid & 63, cq = tid >> 6;       // thread owns (pos, 48 ch)
    int c0 = cq * 48;
    float pool[48];
#pragma unroll
    for (int k = 0; k < 48; k++) pool[k] = -3.4e38f;
    float gs[2] = {0, 0}, gq[2] = {0, 0};

    int arow = l & 15;
    int ahk  = (l >> 4) << 3;
    int bc   = (l & 7) + ((l >> 4) << 3);
    int bhk  = ((l >> 3) & 1) << 3;

    for (int si = 0; si < 32; si++) {
        int s_ = schunk * 32 + si;
        int m0 = s_ * NPTS + nc * 64;

        // producer: h2 -> GN1+ReLU -> bf16 split
        for (int e = tid; e < 3072; e += 256) {
            int pos = e & 63, kp = e >> 6;
            int k0 = 2 * kp, k1 = k0 + 1;
            float o0 = h2[((size_t)b * 96 + k0) * MPOS + m0 + pos];
            float o1 = h2[((size_t)b * 96 + k1) * MPOS + m0 + pos];
            o0 = fmaxf(fmaf(o0, sc[k0], shf[k0]), 0.f);
            o1 = fmaxf(fmaf(o1, sc[k1], shf[k1]), 0.f);
            uint32_t hw, lw;
            split2(o0, o1, &hw, &lw);
            *(uint32_t*)(sm + pos * SAB + kp * 4) = hw;
            *(uint32_t*)(sm + C3_ALO + pos * SAB + kp * 4) = lw;
        }
        __syncthreads();

        float acc[2][6][4];
#pragma unroll
        for (int mi = 0; mi < 2; mi++)
#pragma unroll
            for (int nj = 0; nj < 6; nj++)
#pragma unroll
                for (int r = 0; r < 4; r++) acc[mi][nj][r] = 0.f;

#pragma unroll 1
        for (int ks = 0; ks < 6; ks++) {
            int k0 = ks * 16;
            uint32_t ah[2][4], al[2][4], bh[6][2], bl[6][2];
#pragma unroll
            for (int mi = 0; mi < 2; mi++) {
                uint32_t ad = sb + (mw * 32 + mi * 16 + arow) * SAB + (k0 + ahk) * 2;
                ldmat4(ah[mi], ad);
                ldmat4(al[mi], ad + C3_ALO);
            }
#pragma unroll
            for (int np = 0; np < 3; np++) {
                uint32_t bd = sb + C3_WHI + (nw * 48 + np * 16 + bc) * SAB + (k0 + bhk) * 2;
                uint32_t r4[4];
                ldmat4(r4, bd);
                bh[2 * np][0] = r4[0]; bh[2 * np][1] = r4[1];
                bh[2 * np + 1][0] = r4[2]; bh[2 * np + 1][1] = r4[3];
                ldmat4(r4, bd + (C3_WLO - C3_WHI));
                bl[2 * np][0] = r4[0]; bl[2 * np][1] = r4[1];
                bl[2 * np + 1][0] = r4[2]; bl[2 * np + 1][1] = r4[3];
            }
#pragma unroll
            for (int mi = 0; mi < 2; mi++)
#pragma unroll
                for (int nj = 0; nj < 6; nj++) {
                    mma16816(acc[mi][nj], ah[mi], bh[nj]);
                    mma16816(acc[mi][nj], al[mi], bh[nj]);
                    mma16816(acc[mi][nj], ah[mi], bl[nj]);
                }
        }

        int g2 = l >> 2, t4 = l & 3;
#pragma unroll
        for (int mi = 0; mi < 2; mi++)
#pragma unroll
            for (int nj = 0; nj < 6; nj++) {
                int row = mw * 32 + mi * 16 + g2;
                int col = nw * 48 + nj * 8 + t4 * 2;
                float bv0 = biasS[col], bv1 = biasS[col + 1];
                stage[col * 68 + row]           = acc[mi][nj][0] + bv0;
                stage[(col + 1) * 68 + row]     = acc[mi][nj][1] + bv1;
                stage[col * 68 + row + 8]       = acc[mi][nj][2] + bv0;
                stage[(col + 1) * 68 + row + 8] = acc[mi][nj][3] + bv1;
            }
        __syncthreads();

        // pooled-max + stage-2 stats from staged tile
#pragma unroll
        for (int k = 0; k < 48; k++) {
            float v = stage[(c0 + k) * 68 + pos_t];
            pool[k] = fmaxf(pool[k], v);
            gs[k / 24] += v;
            gq[k / 24] += v * v;
        }
        __syncthreads();
    }

    // write pooled partial (exclusive ownership — plain stores)
    int n = nc * 64 + pos_t;
#pragma unroll
    for (int k = 0; k < 48; k++)
        poolpart[(((size_t)schunk * BATCH + b) * C3 + c0 + k) * NPTS + n] = pool[k];

    // reduce stats (cq constant within warp)
#pragma unroll
    for (int g = 0; g < 2; g++) {
        for (int off = 16; off; off >>= 1) {
            gs[g] += __shfl_down_sync(0xffffffffu, gs[g], off);
            gq[g] += __shfl_down_sync(0xffffffffu, gq[g], off);
        }
    }
    if (l == 0) {
#pragma unroll
        for (int g = 0; g < 2; g++) {
            int gg = cq * 2 + g;
            atomicAdd(&stats2[((size_t)(b * GRP + gg)) * 2 + 0], (double)gs[g]);
            atomicAdd(&stats2[((size_t)(b * GRP + gg)) * 2 + 1], (double)gq[g]);
        }
    }
}

// ---------------------------------------------------------------------------
// Pool fix: merge 2 s-chunk partials, apply GN(stage2)+ReLU (scale>0)
// ---------------------------------------------------------------------------
__global__ void poolfix_kernel(const float* __restrict__ gamma,
                               const float* __restrict__ beta,
                               const float* __restrict__ mr) {
    int q = blockIdx.x * 256 + threadIdx.x;
    int b = q / (C3 * NPTS);
    int r = q % (C3 * NPTS);
    int c = r / NPTS;
    float raw = fmaxf(d_poolpart[(size_t)(0 * BATCH + b) * C3 * NPTS + r],
                      d_poolpart[(size_t)(1 * BATCH + b) * C3 * NPTS + r]);
    int g = c / 24;
    float s = mr[(b * GRP + g) * 2 + 1] * gamma[c];
    float t = beta[c] - mr[(b * GRP + g) * 2 + 0] * s;
    d_pool[q] = fmaxf(fmaf(raw, s, t), 0.f);
}

// ---------------------------------------------------------------------------
// fp32 GEMM for small post-MLP stages (known-good from R2)
// ---------------------------------------------------------------------------
__global__ void __launch_bounds__(256, 2)
mlp_gemm(const float* __restrict__ in, const float* __restrict__ w,
         const float* __restrict__ bias, float* __restrict__ outbuf,
         int CIN, int COUTtot, int Mtot,
         const float* __restrict__ gamma, const float* __restrict__ beta,
         const float* __restrict__ mr_in, int in_cpg,
         double* __restrict__ stats_out, int out_cpg) {
    extern __shared__ float fsm[];
    float* xs  = fsm;
    float* wsT = fsm + 96 * 128;
    float* sc  = wsT + 96 * 97;
    float* shf = sc + 192;

    int b = blockIdx.y;
    int m0 = blockIdx.x * 128;
    int co0 = blockIdx.z * 96;
    int tid = threadIdx.x;
    int tc = tid >> 4, tp = tid & 15;

    if (gamma) {
        for (int k = tid; k < CIN; k += 256) {
            int g = k / in_cpg;
            float mean = mr_in[(b * GRP + g) * 2 + 0];
            float rstd = mr_in[(b * GRP + g) * 2 + 1];
            float s = rstd * gamma[k];
            sc[k]  = s;
            shf[k] = beta[k] - mean * s;
        }
    }
    __syncthreads();

    float acc[6][8];
#pragma unroll
    for (int ci = 0; ci < 6; ci++)
#pragma unroll
        for (int pi = 0; pi < 8; pi++) acc[ci][pi] = 0.f;

    for (int kc = 0; kc < CIN; kc += 96) {
        for (int i = tid; i < 96 * 96; i += 256) {
            int c = i / 96, kk = i % 96;
            wsT[kk * 97 + c] = w[(size_t)(co0 + c) * CIN + kc + kk];
        }
        const float* inb = in + ((size_t)b * CIN + kc) * Mtot + m0;
        for (int i = tid; i < 96 * 32; i += 256) {
            int kk = i >> 5, p4 = i & 31;
            float4 v = ((const float4*)(inb + (size_t)kk * Mtot))[p4];
            if (gamma) {
                int k = kc + kk;
                float s = sc[k], h = shf[k];
                v.x = fmaxf(fmaf(v.x, s, h), 0.f);
                v.y = fmaxf(fmaf(v.y, s, h), 0.f);
                v.z = fmaxf(fmaf(v.z, s, h), 0.f);
                v.w = fmaxf(fmaf(v.w, s, h), 0.f);
            }
            ((float4*)(xs + kk * 128))[p4] = v;
        }
        __syncthreads();
#pragma unroll 8
        for (int kk = 0; kk < 96; kk++) {
            float4 xa = *(const float4*)&xs[kk * 128 + tp * 8];
            float4 xb = *(const float4*)&xs[kk * 128 + tp * 8 + 4];
            float wr[6];
#pragma unroll
            for (int ci = 0; ci < 6; ci++) wr[ci] = wsT[kk * 97 + tc * 6 + ci];
#pragma unroll
            for (int ci = 0; ci < 6; ci++) {
                acc[ci][0] = fmaf(wr[ci], xa.x, acc[ci][0]);
                acc[ci][1] = fmaf(wr[ci], xa.y, acc[ci][1]);
                acc[ci][2] = fmaf(wr[ci], xa.z, acc[ci][2]);
                acc[ci][3] = fmaf(wr[ci], xa.w, acc[ci][3]);
                acc[ci][4] = fmaf(wr[ci], xb.x, acc[ci][4]);
                acc[ci][5] = fmaf(wr[ci], xb.y, acc[ci][5]);
                acc[ci][6] = fmaf(wr[ci], xb.z, acc[ci][6]);
                acc[ci][7] = fmaf(wr[ci], xb.w, acc[ci][7]);
            }
        }
        __syncthreads();
    }

    int cbase = co0 + tc * 6;
    float gsum = 0.f, gsq = 0.f;
#pragma unroll
    for (int ci = 0; ci < 6; ci++) {
        float bv = bias[cbase + ci];
        float v0 = acc[ci][0] + bv, v1 = acc[ci][1] + bv, v2 = acc[ci][2] + bv, v3 = acc[ci][3] + bv;
        float v4 = acc[ci][4] + bv, v5 = acc[ci][5] + bv, v6 = acc[ci][6] + bv, v7 = acc[ci][7] + bv;
        float* orow = outbuf + ((size_t)b * COUTtot + cbase + ci) * Mtot + m0 + tp * 8;
        ((float4*)orow)[0] = make_float4(v0, v1, v2, v3);
        ((float4*)orow)[1] = make_float4(v4, v5, v6, v7);
        if (stats_out) {
            gsum += v0 + v1 + v2 + v3 + v4 + v5 + v6 + v7;
            gsq  += v0 * v0 + v1 * v1 + v2 * v2 + v3 * v3 + v4 * v4 + v5 * v5 + v6 * v6 + v7 * v7;
        }
    }
    if (stats_out) {
        for (int off = 16; off; off >>= 1) {
            gsum += __shfl_down_sync(0xffffffffu, gsum, off);
            gsq  += __shfl_down_sync(0xffffffffu, gsq, off);
        }
        if ((tid & 31) == 0) {
            int g = cbase / out_cpg;
            atomicAdd(&stats_out[((size_t)(b * GRP + g)) * 2 + 0], (double)gsum);
            atomicAdd(&stats_out[((size_t)(b * GRP + g)) * 2 + 1], (double)gsq);
        }
    }
}

// ---------------------------------------------------------------------------
// Final stage (known-good): GN(stage4)+ReLU, conv 96->96, L2-normalize
// ---------------------------------------------------------------------------
__global__ void __launch_bounds__(256, 2)
final_kernel(const float* __restrict__ in, const float* __restrict__ w,
             const float* __restrict__ bias, const float* __restrict__ gamma,
             const float* __restrict__ beta, const float* __restrict__ mr,
             float* __restrict__ out) {
    extern __shared__ float fsm[];
    float* xs  = fsm;
    float* wsT = fsm + 96 * 128;
    float* sc  = wsT + 96 * 97;
    float* shf = sc + 192;

    int b = blockIdx.y;
    int m0 = blockIdx.x * 128;
    int tid = threadIdx.x;
    int tc = tid >> 4, tp = tid & 15;

    for (int k = tid; k < 96; k += 256) {
        int g = k / 12;
        float mean = mr[(b * GRP + g) * 2 + 0];
        float rstd = mr[(b * GRP + g) * 2 + 1];
        float s = rstd * gamma[k];
        sc[k]  = s;
        shf[k] = beta[k] - mean * s;
    }
    __syncthreads();
    for (int i = tid; i < 96 * 96; i += 256) {
        int c = i / 96, kk = i % 96;
        wsT[kk * 97 + c] = w[(size_t)c * 96 + kk];
    }
    const float* inb = in + (size_t)b * 96 * NPTS + m0;
    for (int i = tid; i < 96 * 32; i += 256) {
        int kk = i >> 5, p4 = i & 31;
        float4 v = ((const float4*)(inb + (size_t)kk * NPTS))[p4];
        float s = sc[kk], h = shf[kk];
        v.x = fmaxf(fmaf(v.x, s, h), 0.f);
        v.y = fmaxf(fmaf(v.y, s, h), 0.f);
        v.z = fmaxf(fmaf(v.z, s, h), 0.f);
        v.w = fmaxf(fmaf(v.w, s, h), 0.f);
        ((float4*)(xs + kk * 128))[p4] = v;
    }
    __syncthreads();

    float acc[6][8];
#pragma unroll
    for (int ci = 0; ci < 6; ci++)
#pragma unroll
        for (int pi = 0; pi < 8; pi++) acc[ci][pi] = 0.f;
#pragma unroll 8
    for (int kk = 0; kk < 96; kk++) {
        float4 xa = *(const float4*)&xs[kk * 128 + tp * 8];
        float4 xb = *(const float4*)&xs[kk * 128 + tp * 8 + 4];
        float wr[6];
#pragma unroll
        for (int ci = 0; ci < 6; ci++) wr[ci] = wsT[kk * 97 + tc * 6 + ci];
#pragma unroll
        for (int ci = 0; ci < 6; ci++) {
            acc[ci][0] = fmaf(wr[ci], xa.x, acc[ci][0]);
            acc[ci][1] = fmaf(wr[ci], xa.y, acc[ci][1]);
            acc[ci][2] = fmaf(wr[ci], xa.z, acc[ci][2]);
            acc[ci][3] = fmaf(wr[ci], xa.w, acc[ci][3]);
            acc[ci][4] = fmaf(wr[ci], xb.x, acc[ci][4]);
            acc[ci][5] = fmaf(wr[ci], xb.y, acc[ci][5]);
            acc[ci][6] = fmaf(wr[ci], xb.z, acc[ci][6]);
            acc[ci][7] = fmaf(wr[ci], xb.w, acc[ci][7]);
        }
    }
    __syncthreads();

    float* ob = fsm;
#pragma unroll
    for (int ci = 0; ci < 6; ci++) {
        float bv = bias[tc * 6 + ci];
#pragma unroll
        for (int pi = 0; pi < 8; pi++)
            ob[(tc * 6 + ci) * 129 + tp * 8 + pi] = acc[ci][pi] + bv;
    }
    __syncthreads();

    if (tid < 128) {
        int p = tid;
        float s2 = 0.f;
#pragma unroll
        for (int c = 0; c < 96; c++) {
            float v = ob[c * 129 + p];
            s2 += v * v;
        }
        float rinv = rsqrtf(s2);
        float* op = out + ((size_t)b * NPTS + m0 + p) * 96;
#pragma unroll
        for (int c = 0; c < 96; c++) op[c] = ob[c * 129 + p] * rinv;
    }
}

// ---------------------------------------------------------------------------
// Launch
// ---------------------------------------------------------------------------
extern "C" void kernel_launch(void* const* d_in, const int* in_sizes, int n_in,
                              void* d_out, int out_size) {
    const float* xyz     = (const float*)d_in[0];
    const float* pre_w1  = (const float*)d_in[1];
    const float* pre_b1  = (const float*)d_in[2];
    const float* pre_g1  = (const float*)d_in[3];
    const float* pre_be1 = (const float*)d_in[4];
    const float* pre_w2  = (const float*)d_in[5];
    const float* pre_b2  = (const float*)d_in[6];
    const float* pre_g2  = (const float*)d_in[7];
    const float* pre_be2 = (const float*)d_in[8];
    const float* pre_w3  = (const float*)d_in[9];
    const float* pre_b3  = (const float*)d_in[10];
    const float* pre_g3  = (const float*)d_in[11];
    const float* pre_be3 = (const float*)d_in[12];
    const float* post_w1 = (const float*)d_in[13];
    const float* post_b1 = (const float*)d_in[14];
    const float* post_g1 = (const float*)d_in[15];
    const float* post_be1= (const float*)d_in[16];
    const float* post_w2 = (const float*)d_in[17];
    const float* post_b2 = (const float*)d_in[18];
    const float* post_g2 = (const float*)d_in[19];
    const float* post_be2= (const float*)d_in[20];
    const float* post_w3 = (const float*)d_in[21];
    const float* post_b3 = (const float*)d_in[22];
    float* out = (float*)d_out;

    double* statsP; float* mrP;
    float *h2P, *poolP, *ppP, *p1P, *p2P;
    cudaGetSymbolAddress((void**)&statsP, d_stats);
    cudaGetSymbolAddress((void**)&mrP,    d_mr);
    cudaGetSymbolAddress((void**)&h2P,    d_h2);
    cudaGetSymbolAddress((void**)&poolP,  d_pool);
    cudaGetSymbolAddress((void**)&ppP,    d_poolpart);
    cudaGetSymbolAddress((void**)&p1P,    d_p1);
    cudaGetSymbolAddress((void**)&p2P,    d_p2);

    const int FSMEM = (96 * 128 + 96 * 97 + 2 * 192) * (int)sizeof(float); // 87936
    cudaFuncSetAttribute(mlp_gemm,     cudaFuncAttributeMaxDynamicSharedMemorySize, FSMEM);
    cudaFuncSetAttribute(final_kernel, cudaFuncAttributeMaxDynamicSharedMemorySize, FSMEM);
    cudaFuncSetAttribute(conv2_mma,    cudaFuncAttributeMaxDynamicSharedMemorySize, C2_SMEM);
    cudaFuncSetAttribute(conv3_mma,    cudaFuncAttributeMaxDynamicSharedMemorySize, C3_SMEM);

    const int SOFF = BATCH * GRP * 2;

    init_kernel<<<1, 256>>>();
    ballquery_kernel<<<512, 256>>>(xyz);
    conv1_stats_kernel<<<(BATCH * MPOS) / 256, 256>>>(xyz, pre_w1, pre_b1, statsP + 0 * SOFF);
    finalize_kernel<<<1, 32>>>(0, 12.0 * MPOS);

    // conv2: fused conv1 recompute + GN0+ReLU -> bf16x3 mma.sync -> h2 + stage1 stats
    conv2_mma<<<dim3(74, BATCH), 256, C2_SMEM>>>(
        xyz, pre_w1, pre_b1, pre_w2, pre_b2,
        pre_g1, pre_be1, mrP + 0 * SOFF, statsP + 1 * SOFF, h2P);
    finalize_kernel<<<1, 32>>>(1, 12.0 * MPOS);

    // conv3: GN1+ReLU -> bf16x3 mma.sync -> register pooled max + stage2 stats
    conv3_mma<<<dim3(32, BATCH, 2), 256, C3_SMEM>>>(
        h2P, pre_w3, pre_b3, pre_g2, pre_be2,
        mrP + 1 * SOFF, statsP + 2 * SOFF, ppP);
    finalize_kernel<<<1, 32>>>(2, 24.0 * MPOS);

    poolfix_kernel<<<(BATCH * C3 * NPTS) / 256, 256>>>(pre_g3, pre_be3, mrP + 2 * SOFF);

    // post1: 192 -> 192 (fp32), stats -> stage3
    mlp_gemm<<<dim3(NPTS / 128, BATCH, 2), 256, FSMEM>>>(
        poolP, post_w1, post_b1, p1P, 192, 192, NPTS,
        (const float*)0, (const float*)0, (const float*)0, 0, statsP + 3 * SOFF, 24);
    finalize_kernel<<<1, 32>>>(3, 24.0 * NPTS);

    // post2: 192 -> 96 (fp32), input GN(stage3), stats -> stage4
    mlp_gemm<<<dim3(NPTS / 128, BATCH, 1), 256, FSMEM>>>(
        p1P, post_w2, post_b2, p2P, 192, 96, NPTS,
        post_g1, post_be1, mrP + 3 * SOFF, 24, statsP + 4 * SOFF, 12);
    finalize_kernel<<<1, 32>>>(4, 12.0 * NPTS);

    final_kernel<<<dim3(NPTS / 128, BATCH, 1), 256, FSMEM>>>(
        p2P, post_w3, post_b3, post_g2, post_be2, mrP + 4 * SOFF, out);
}

// round 7
// speedup vs baseline: 1.8897x; 1.3314x over previous
#include <cuda_runtime.h>
#include <cuda_bf16.h>
#include <math.h>
#include <stdint.h>

#define BATCH 2
#define NPTS  2048
#define NS    64
#define MPOS  (NS * NPTS)   // 131072 positions per batch
#define C1    96
#define C3    192
#define GRP   8
#define R2    0.09f
#define SAB   208           // bf16 row stride in bytes (104 elements)

// ---------------------------------------------------------------------------
// Static device scratch
// ---------------------------------------------------------------------------
__device__ __align__(256) int    d_idx[BATCH * NS * NPTS];
__device__ __align__(256) float  d_h2[(size_t)BATCH * C1 * MPOS];      // raw conv2 out [b][c][m]
__device__ __align__(256) float  d_poolpart[2 * BATCH * C3 * NPTS];    // per-schunk biased max
__device__ __align__(256) float  d_p1[(size_t)BATCH * C3 * NPTS];
__device__ __align__(256) float  d_p2[(size_t)BATCH * C1 * NPTS];
__device__ __align__(256) double d_stats[5 * BATCH * GRP * 2];
__device__ float* d_dummy_sink;

// ---------------------------------------------------------------------------
// Helpers
// ---------------------------------------------------------------------------
__device__ __forceinline__ uint32_t s2u(const void* p) {
    uint32_t a;
    asm("{ .reg .u64 t; cvta.to.shared.u64 t, %1; cvt.u32.u64 %0, t; }" : "=r"(a) : "l"(p));
    return a;
}
__device__ __forceinline__ void ldmat4(uint32_t* r, uint32_t addr) {
    asm volatile("ldmatrix.sync.aligned.m8n8.x4.shared.b16 {%0,%1,%2,%3}, [%4];"
                 : "=r"(r[0]), "=r"(r[1]), "=r"(r[2]), "=r"(r[3]) : "r"(addr));
}
__device__ __forceinline__ void mma16816(float* c, const uint32_t* a, const uint32_t* b) {
    asm volatile("mma.sync.aligned.m16n8k16.row.col.f32.bf16.bf16.f32 "
                 "{%0,%1,%2,%3}, {%4,%5,%6,%7}, {%8,%9}, {%0,%1,%2,%3};"
                 : "+f"(c[0]), "+f"(c[1]), "+f"(c[2]), "+f"(c[3])
                 : "r"(a[0]), "r"(a[1]), "r"(a[2]), "r"(a[3]), "r"(b[0]), "r"(b[1]));
}
__device__ __forceinline__ void split2(float x0, float x1, uint32_t* hi, uint32_t* lo) {
    __nv_bfloat16 h0 = __float2bfloat16_rn(x0);
    __nv_bfloat16 h1 = __float2bfloat16_rn(x1);
    float r0 = x0 - __bfloat162float(h0);
    float r1 = x1 - __bfloat162float(h1);
    __nv_bfloat16 l0 = __float2bfloat16_rn(r0);
    __nv_bfloat16 l1 = __float2bfloat16_rn(r1);
    *hi = (uint32_t)__bfloat16_as_ushort(h0) | ((uint32_t)__bfloat16_as_ushort(h1) << 16);
    *lo = (uint32_t)__bfloat16_as_ushort(l0) | ((uint32_t)__bfloat16_as_ushort(l1) << 16);
}
// inline GN finalize: mean/scale from double stats
__device__ __forceinline__ void gn_const(const double* __restrict__ stats, double invcnt,
                                         int b, int g, const float* __restrict__ gamma,
                                         const float* __restrict__ beta, int k,
                                         float* s_out, float* h_out) {
    const double* sp = stats + ((size_t)(b * GRP + g)) * 2;
    double mean = sp[0] * invcnt;
    double var  = sp[1] * invcnt - mean * mean;
    if (var < 0.0) var = 0.0;
    float rstd = (float)(1.0 / sqrt(var + 1e-5));
    float s = rstd * gamma[k];
    *s_out = s;
    *h_out = beta[k] - (float)mean * s;
}

// ---------------------------------------------------------------------------
// Dummy kernels (ncu launch-index positioning: puts conv3_mma at launch #6)
// ---------------------------------------------------------------------------
__global__ void dummy_kernel() {}

// ---------------------------------------------------------------------------
// Ball query + stats zeroing (block 0)
// ---------------------------------------------------------------------------
__global__ void ballquery_kernel(const float* __restrict__ xyz) {
    if (blockIdx.x == 0 && threadIdx.x < 5 * BATCH * GRP * 2)
        d_stats[threadIdx.x] = 0.0;
    int warp = (blockIdx.x * blockDim.x + threadIdx.x) >> 5;
    int lane = threadIdx.x & 31;
    if (warp >= BATCH * NPTS) return;
    int b = warp / NPTS, i = warp % NPTS;
    const float* base = xyz + (size_t)b * NPTS * 3;
    float cx = base[i * 3 + 0], cy = base[i * 3 + 1], cz = base[i * 3 + 2];
    int count = 0, first = 0;
    for (int jb = 0; jb < NPTS; jb += 32) {
        int j = jb + lane;
        float dx = base[j * 3 + 0] - cx;
        float dy = base[j * 3 + 1] - cy;
        float dz = base[j * 3 + 2] - cz;
        float d2 = dx * dx + dy * dy + dz * dz;
        bool ok = (d2 <= R2);
        unsigned mask = __ballot_sync(0xffffffffu, ok);
        if (ok) {
            int pos = count + __popc(mask & ((1u << lane) - 1u));
            if (pos < NS) d_idx[((size_t)(b * NS + pos)) * NPTS + i] = j;
        }
        if (count == 0 && mask) first = jb + __ffs(mask) - 1;
        count += __popc(mask);
        if (count >= NS) break;
    }
    for (int p = count + lane; p < NS; p += 32)
        d_idx[((size_t)(b * NS + p)) * NPTS + i] = first;
}

// ---------------------------------------------------------------------------
// Conv1 stats-only pass (stage-0 GN stats; no h1 store)
// ---------------------------------------------------------------------------
__global__ void conv1_stats_kernel(const float* __restrict__ xyz,
                                   const float* __restrict__ w1,
                                   const float* __restrict__ b1,
                                   double* __restrict__ stats0) {
    __shared__ float ws[C1 * 6];
    __shared__ float bs[C1];
    __shared__ float red[8][16];
    int tid = threadIdx.x;
    for (int i = tid; i < C1 * 6; i += 256) ws[i] = w1[i];
    if (tid < C1) bs[tid] = b1[tid];
    __syncthreads();

    int q = blockIdx.x * 256 + tid;
    int b = q / MPOS, m = q % MPOS;
    int s = m / NPTS, n = m % NPTS;
    int j = d_idx[((size_t)(b * NS + s)) * NPTS + n];
    const float* xb = xyz + (size_t)b * NPTS * 3;
    float f0 = xb[n * 3 + 0], f1 = xb[n * 3 + 1], f2 = xb[n * 3 + 2];
    float f3 = xb[j * 3 + 0] - f0, f4 = xb[j * 3 + 1] - f1, f5 = xb[j * 3 + 2] - f2;

    float sum8[8], sq8[8];
#pragma unroll
    for (int g = 0; g < 8; g++) { sum8[g] = 0.f; sq8[g] = 0.f; }
#pragma unroll
    for (int c = 0; c < C1; c++) {
        const float* wr = ws + c * 6;
        float o = bs[c];
        o = fmaf(wr[0], f0, o); o = fmaf(wr[1], f1, o); o = fmaf(wr[2], f2, o);
        o = fmaf(wr[3], f3, o); o = fmaf(wr[4], f4, o); o = fmaf(wr[5], f5, o);
        sum8[c / 12] += o;
        sq8[c / 12]  += o * o;
    }
#pragma unroll
    for (int g = 0; g < 8; g++) {
        for (int off = 16; off; off >>= 1) {
            sum8[g] += __shfl_down_sync(0xffffffffu, sum8[g], off);
            sq8[g]  += __shfl_down_sync(0xffffffffu, sq8[g], off);
        }
    }
    int wid = tid >> 5, lane = tid & 31;
    if (lane == 0) {
#pragma unroll
        for (int g = 0; g < 8; g++) {
            red[wid][g * 2 + 0] = sum8[g];
            red[wid][g * 2 + 1] = sq8[g];
        }
    }
    __syncthreads();
    if (tid < 16) {
        float acc = 0.f;
#pragma unroll
        for (int w = 0; w < 8; w++) acc += red[w][tid];
        int g = tid >> 1, which = tid & 1;
        int bb = (blockIdx.x * 256) / MPOS;
        atomicAdd(&stats0[((size_t)(bb * GRP + g)) * 2 + which], (double)acc);
    }
}

// ---------------------------------------------------------------------------
// conv2 via mma.sync (structure from R5) + inline stage-0 finalize
// ---------------------------------------------------------------------------
#define C2_ALO 26624
#define C2_WHI 53248
#define C2_WLO 73216
#define C2_MSC 93184
#define C2_SMEM 100352

__global__ void __launch_bounds__(256, 1)
conv2_mma(const float* __restrict__ xyz,
          const float* __restrict__ w1, const float* __restrict__ b1,
          const float* __restrict__ w2, const float* __restrict__ b2,
          const float* __restrict__ gamma, const float* __restrict__ beta,
          const double* __restrict__ stats0, double invcnt0,
          double* __restrict__ stats1, float* __restrict__ h2) {
    extern __shared__ char sm[];
    uint32_t sb = s2u(sm);
    float* stage = (float*)sm;                 // 96 x 132 f32 (overlaps A)
    float* sc    = (float*)(sm + C2_MSC);      // 96
    float* shf   = sc + 96;
    float* biasS = shf + 96;                   // 96
    float* w1s   = biasS + 96;                 // 576
    float* b1s   = w1s + 576;                  // 96
    float* feat  = b1s + 96;                   // 128*6

    int tid = threadIdx.x, w = tid >> 5, l = tid & 31;
    int b = blockIdx.y;
    int mw = w & 3, nw = w >> 2;               // warp: 32 pos x 48 ch

    for (int k = tid; k < 96; k += 256)
        gn_const(stats0, invcnt0, b, k / 12, gamma, beta, k, &sc[k], &shf[k]);
    if (tid < 96) biasS[tid] = b2[tid];
    for (int i = tid; i < 576; i += 256) w1s[i] = w1[i];
    if (tid < 96) b1s[tid] = b1[tid];
    for (int e = tid; e < 96 * 48; e += 256) {
        int kp = e % 48, c = e / 48;
        float2 v = *(const float2*)(w2 + (size_t)c * 96 + 2 * kp);
        uint32_t hw, lw;
        split2(v.x, v.y, &hw, &lw);
        *(uint32_t*)(sm + C2_WHI + c * SAB + kp * 4) = hw;
        *(uint32_t*)(sm + C2_WLO + c * SAB + kp * 4) = lw;
    }
    __syncthreads();

    float gsum[4] = {0, 0, 0, 0}, gsq[4] = {0, 0, 0, 0};
    int pos_t = tid & 127, chalf = tid >> 7;

    for (int t = blockIdx.x; t < 1024; t += gridDim.x) {
        int m0 = t * 128;
        if (tid < 128) {
            int s_ = m0 >> 11, n = (m0 & 2047) + tid;
            int j = d_idx[((size_t)(b * NS + s_)) * NPTS + n];
            const float* xb = xyz + (size_t)b * NPTS * 3;
            float f0 = xb[n * 3 + 0], f1 = xb[n * 3 + 1], f2 = xb[n * 3 + 2];
            feat[tid * 6 + 0] = f0;
            feat[tid * 6 + 1] = f1;
            feat[tid * 6 + 2] = f2;
            feat[tid * 6 + 3] = xb[j * 3 + 0] - f0;
            feat[tid * 6 + 4] = xb[j * 3 + 1] - f1;
            feat[tid * 6 + 5] = xb[j * 3 + 2] - f2;
        }
        __syncthreads();
        for (int e = tid; e < 6144; e += 256) {
            int kp = e % 48, pos = e / 48;
            int k0 = 2 * kp, k1 = k0 + 1;
            const float* fr = feat + pos * 6;
            float o0 = b1s[k0], o1 = b1s[k1];
            const float* wr0 = w1s + k0 * 6;
            const float* wr1 = w1s + k1 * 6;
#pragma unroll
            for (int j2 = 0; j2 < 6; j2++) {
                float fv = fr[j2];
                o0 = fmaf(wr0[j2], fv, o0);
                o1 = fmaf(wr1[j2], fv, o1);
            }
            o0 = fmaxf(fmaf(o0, sc[k0], shf[k0]), 0.f);
            o1 = fmaxf(fmaf(o1, sc[k1], shf[k1]), 0.f);
            uint32_t hw, lw;
            split2(o0, o1, &hw, &lw);
            *(uint32_t*)(sm + pos * SAB + kp * 4) = hw;
            *(uint32_t*)(sm + C2_ALO + pos * SAB + kp * 4) = lw;
        }
        __syncthreads();

        float acc[2][6][4];
#pragma unroll
        for (int mi = 0; mi < 2; mi++)
#pragma unroll
            for (int nj = 0; nj < 6; nj++)
#pragma unroll
                for (int r = 0; r < 4; r++) acc[mi][nj][r] = 0.f;

        int arow = l & 15;
        int ahk  = (l >> 4) << 3;
        int bc   = (l & 7) + ((l >> 4) << 3);
        int bhk  = ((l >> 3) & 1) << 3;
#pragma unroll 1
        for (int ks = 0; ks < 6; ks++) {
            int k0 = ks * 16;
            uint32_t ah[2][4], al[2][4], bh[6][2], bl[6][2];
#pragma unroll
            for (int mi = 0; mi < 2; mi++) {
                uint32_t ad = sb + (mw * 32 + mi * 16 + arow) * SAB + (k0 + ahk) * 2;
                ldmat4(ah[mi], ad);
                ldmat4(al[mi], ad + C2_ALO);
            }
#pragma unroll
            for (int np = 0; np < 3; np++) {
                uint32_t bd = sb + C2_WHI + (nw * 48 + np * 16 + bc) * SAB + (k0 + bhk) * 2;
                uint32_t r4[4];
                ldmat4(r4, bd);
                bh[2 * np][0] = r4[0]; bh[2 * np][1] = r4[1];
                bh[2 * np + 1][0] = r4[2]; bh[2 * np + 1][1] = r4[3];
                ldmat4(r4, bd + (C2_WLO - C2_WHI));
                bl[2 * np][0] = r4[0]; bl[2 * np][1] = r4[1];
                bl[2 * np + 1][0] = r4[2]; bl[2 * np + 1][1] = r4[3];
            }
#pragma unroll
            for (int mi = 0; mi < 2; mi++)
#pragma unroll
                for (int nj = 0; nj < 6; nj++) {
                    mma16816(acc[mi][nj], ah[mi], bh[nj]);
                    mma16816(acc[mi][nj], al[mi], bh[nj]);
                    mma16816(acc[mi][nj], ah[mi], bl[nj]);
                }
        }
        __syncthreads();   // A reads done; stage may overwrite

        int g2 = l >> 2, t4 = l & 3;
#pragma unroll
        for (int mi = 0; mi < 2; mi++)
#pragma unroll
            for (int nj = 0; nj < 6; nj++) {
                int row = mw * 32 + mi * 16 + g2;
                int col = nw * 48 + nj * 8 + t4 * 2;
                float bv0 = biasS[col], bv1 = biasS[col + 1];
                stage[col * 132 + row]           = acc[mi][nj][0] + bv0;
                stage[(col + 1) * 132 + row]     = acc[mi][nj][1] + bv1;
                stage[col * 132 + row + 8]       = acc[mi][nj][2] + bv0;
                stage[(col + 1) * 132 + row + 8] = acc[mi][nj][3] + bv1;
            }
        __syncthreads();

        for (int e = tid; e < 3072; e += 256) {
            int c = e >> 5, pq = e & 31;
            float4 v = *(float4*)(stage + c * 132 + pq * 4);
            *(float4*)(h2 + ((size_t)b * 96 + c) * MPOS + m0 + pq * 4) = v;
        }
        {
            int c0 = chalf * 48;
#pragma unroll
            for (int k = 0; k < 48; k++) {
                float v = stage[(c0 + k) * 132 + pos_t];
                gsum[k / 12] += v;
                gsq[k / 12]  += v * v;
            }
        }
        __syncthreads();
    }

#pragma unroll
    for (int g = 0; g < 4; g++) {
        for (int off = 16; off; off >>= 1) {
            gsum[g] += __shfl_down_sync(0xffffffffu, gsum[g], off);
            gsq[g]  += __shfl_down_sync(0xffffffffu, gsq[g], off);
        }
    }
    if (l == 0) {
        int gb = chalf * 4;
#pragma unroll
        for (int g = 0; g < 4; g++) {
            atomicAdd(&stats1[((size_t)(b * GRP + gb + g)) * 2 + 0], (double)gsum[g]);
            atomicAdd(&stats1[((size_t)(b * GRP + gb + g)) * 2 + 1], (double)gsq[g]);
        }
    }
}

// ---------------------------------------------------------------------------
// conv3 via mma.sync, restructured:
//  - pooled max + stats in FRAGMENT REGISTERS (no stage buffer, 1 fewer sync)
//  - register prefetch of next s-iteration's h2 overlaps MMA
//  - inline stage-1 finalize
// grid = (32 n-chunks, 2 batches, 2 s-chunks), 32 si per block.
// SMEM: A_hi@0 (13312), A_lo@13312, W_hi@26624 (39936), W_lo@66560, misc@106496
// ---------------------------------------------------------------------------
#define C3_ALO 13312
#define C3_WHI 26624
#define C3_WLO 66560
#define C3_MSC 106496
#define C3_SMEM 108032

__global__ void __launch_bounds__(256, 1)
conv3_mma(const float* __restrict__ h2,
          const float* __restrict__ w3, const float* __restrict__ b3,
          const float* __restrict__ gamma, const float* __restrict__ beta,
          const double* __restrict__ stats1, double invcnt1,
          double* __restrict__ stats2, float* __restrict__ poolpart) {
    extern __shared__ char sm[];
    uint32_t sb = s2u(sm);
    float* sc    = (float*)(sm + C3_MSC);      // 96
    float* shf   = sc + 96;
    float* biasS = shf + 96;                   // 192

    int tid = threadIdx.x, w = tid >> 5, l = tid & 31;
    int nc = blockIdx.x, b = blockIdx.y, schunk = blockIdx.z;
    int mw = w & 1, nw = w >> 1;               // warp: 32 pos x 48 ch

    for (int k = tid; k < 96; k += 256)
        gn_const(stats1, invcnt1, b, k / 12, gamma, beta, k, &sc[k], &shf[k]);
    if (tid < 192) biasS[tid] = b3[tid];
    for (int e = tid; e < 192 * 48; e += 256) {
        int kp = e % 48, c = e / 48;
        float2 v = *(const float2*)(w3 + (size_t)c * 96 + 2 * kp);
        uint32_t hw, lw;
        split2(v.x, v.y, &hw, &lw);
        *(uint32_t*)(sm + C3_WHI + c * SAB + kp * 4) = hw;
        *(uint32_t*)(sm + C3_WLO + c * SAB + kp * 4) = lw;
    }
    __syncthreads();

    int g2 = l >> 2, t4 = l & 3;
    int arow = l & 15;
    int ahk  = (l >> 4) << 3;
    int bc   = (l & 7) + ((l >> 4) << 3);
    int bhk  = ((l >> 3) & 1) << 3;

    // per-thread bias for its fragment columns
    float bias_r[6][2];
#pragma unroll
    for (int nj = 0; nj < 6; nj++) {
        int col = nw * 48 + nj * 8 + t4 * 2;
        bias_r[nj][0] = biasS[col];
        bias_r[nj][1] = biasS[col + 1];
    }

    float pool[2][6][4];
#pragma unroll
    for (int mi = 0; mi < 2; mi++)
#pragma unroll
        for (int nj = 0; nj < 6; nj++)
#pragma unroll
            for (int r = 0; r < 4; r++) pool[mi][nj][r] = -3.4e38f;
    float gs[2] = {0, 0}, gq[2] = {0, 0};

    const float* hb = h2 + (size_t)b * 96 * MPOS;
    float pre0[12], pre1[12];

    // initial prefetch (si = 0)
    {
        int m0 = (schunk * 32) * NPTS + nc * 64;
#pragma unroll
        for (int i = 0; i < 12; i++) {
            int e = tid + i * 256;
            int pos = e & 63, kp = e >> 6;
            pre0[i] = hb[(size_t)(2 * kp) * MPOS + m0 + pos];
            pre1[i] = hb[(size_t)(2 * kp + 1) * MPOS + m0 + pos];
        }
    }

    for (int si = 0; si < 32; si++) {
        // producer: GN1+ReLU + split from prefetched registers
#pragma unroll
        for (int i = 0; i < 12; i++) {
            int e = tid + i * 256;
            int pos = e & 63, kp = e >> 6;
            int k0 = 2 * kp;
            float o0 = fmaxf(fmaf(pre0[i], sc[k0],     shf[k0]),     0.f);
            float o1 = fmaxf(fmaf(pre1[i], sc[k0 + 1], shf[k0 + 1]), 0.f);
            uint32_t hw, lw;
            split2(o0, o1, &hw, &lw);
            *(uint32_t*)(sm + pos * SAB + kp * 4) = hw;
            *(uint32_t*)(sm + C3_ALO + pos * SAB + kp * 4) = lw;
        }
        __syncthreads();

        // prefetch next si (LDG latency overlaps MMA below)
        if (si + 1 < 32) {
            int m1 = (schunk * 32 + si + 1) * NPTS + nc * 64;
#pragma unroll
            for (int i = 0; i < 12; i++) {
                int e = tid + i * 256;
                int pos = e & 63, kp = e >> 6;
                pre0[i] = hb[(size_t)(2 * kp) * MPOS + m1 + pos];
                pre1[i] = hb[(size_t)(2 * kp + 1) * MPOS + m1 + pos];
            }
        }

        float acc[2][6][4];
#pragma unroll
        for (int mi = 0; mi < 2; mi++)
#pragma unroll
            for (int nj = 0; nj < 6; nj++)
#pragma unroll
                for (int r = 0; r < 4; r++) acc[mi][nj][r] = 0.f;

#pragma unroll 1
        for (int ks = 0; ks < 6; ks++) {
            int k0 = ks * 16;
            uint32_t ah[2][4], al[2][4], bh[6][2], bl[6][2];
#pragma unroll
            for (int mi = 0; mi < 2; mi++) {
                uint32_t ad = sb + (mw * 32 + mi * 16 + arow) * SAB + (k0 + ahk) * 2;
                ldmat4(ah[mi], ad);
                ldmat4(al[mi], ad + C3_ALO);
            }
#pragma unroll
            for (int np = 0; np < 3; np++) {
                uint32_t bd = sb + C3_WHI + (nw * 48 + np * 16 + bc) * SAB + (k0 + bhk) * 2;
                uint32_t r4[4];
                ldmat4(r4, bd);
                bh[2 * np][0] = r4[0]; bh[2 * np][1] = r4[1];
                bh[2 * np + 1][0] = r4[2]; bh[2 * np + 1][1] = r4[3];
                ldmat4(r4, bd + (C3_WLO - C3_WHI));
                bl[2 * np][0] = r4[0]; bl[2 * np][1] = r4[1];
                bl[2 * np + 1][0] = r4[2]; bl[2 * np + 1][1] = r4[3];
            }
#pragma unroll
            for (int mi = 0; mi < 2; mi++)
#pragma unroll
                for (int nj = 0; nj < 6; nj++) {
                    mma16816(acc[mi][nj], ah[mi], bh[nj]);
                    mma16816(acc[mi][nj], al[mi], bh[nj]);
                    mma16816(acc[mi][nj], ah[mi], bl[nj]);
                }
        }
        __syncthreads();   // A reads done; next producer may overwrite

        // pool/stats directly from fragments (bias folded; group idx static)
#pragma unroll
        for (int mi = 0; mi < 2; mi++)
#pragma unroll
            for (int nj = 0; nj < 6; nj++) {
                const int gi = nj / 3;
#pragma unroll
                for (int r = 0; r < 4; r++) {
                    float v = acc[mi][nj][r] + bias_r[nj][r & 1];
                    pool[mi][nj][r] = fmaxf(pool[mi][nj][r], v);
                    gs[gi] += v;
                    gq[gi] = fmaf(v, v, gq[gi]);
                }
            }
    }

    // write pooled partials (exclusive ownership)
#pragma unroll
    for (int mi = 0; mi < 2; mi++)
#pragma unroll
        for (int nj = 0; nj < 6; nj++)
#pragma unroll
            for (int r = 0; r < 4; r++) {
                int col = nw * 48 + nj * 8 + t4 * 2 + (r & 1);
                int row = mw * 32 + mi * 16 + g2 + ((r & 2) ? 8 : 0);
                poolpart[((size_t)(schunk * BATCH + b) * C3 + col) * NPTS + nc * 64 + row] =
                    pool[mi][nj][r];
            }

    // stats reduce (nw constant within warp => groups nw*2 + gi)
#pragma unroll
    for (int g = 0; g < 2; g++) {
        for (int off = 16; off; off >>= 1) {
            gs[g] += __shfl_down_sync(0xffffffffu, gs[g], off);
            gq[g] += __shfl_down_sync(0xffffffffu, gq[g], off);
        }
    }
    if (l == 0) {
#pragma unroll
        for (int g = 0; g < 2; g++) {
            int gg = nw * 2 + g;
            atomicAdd(&stats2[((size_t)(b * GRP + gg)) * 2 + 0], (double)gs[g]);
            atomicAdd(&stats2[((size_t)(b * GRP + gg)) * 2 + 1], (double)gq[g]);
        }
    }
}

// ---------------------------------------------------------------------------
// fp32 GEMM for post-MLP; optional pool-merge (in2) and inline GN finalize
// ---------------------------------------------------------------------------
__global__ void __launch_bounds__(256, 2)
mlp_gemm(const float* __restrict__ in, const float* __restrict__ in2,
         const float* __restrict__ w, const float* __restrict__ bias,
         float* __restrict__ outbuf,
         int CIN, int COUTtot, int Mtot,
         const float* __restrict__ gamma, const float* __restrict__ beta,
         const double* __restrict__ stats_in, double invcnt, int in_cpg,
         double* __restrict__ stats_out, int out_cpg) {
    extern __shared__ float fsm[];
    float* xs  = fsm;
    float* wsT = fsm + 96 * 128;
    float* sc  = wsT + 96 * 97;
    float* shf = sc + 192;

    int b = blockIdx.y;
    int m0 = blockIdx.x * 128;
    int co0 = blockIdx.z * 96;
    int tid = threadIdx.x;
    int tc = tid >> 4, tp = tid & 15;

    if (gamma) {
        for (int k = tid; k < CIN; k += 256)
            gn_const(stats_in, invcnt, b, k / in_cpg, gamma, beta, k, &sc[k], &shf[k]);
    }
    __syncthreads();

    float acc[6][8];
#pragma unroll
    for (int ci = 0; ci < 6; ci++)
#pragma unroll
        for (int pi = 0; pi < 8; pi++) acc[ci][pi] = 0.f;

    for (int kc = 0; kc < CIN; kc += 96) {
        for (int i = tid; i < 96 * 96; i += 256) {
            int c = i / 96, kk = i % 96;
            wsT[kk * 97 + c] = w[(size_t)(co0 + c) * CIN + kc + kk];
        }
        const float* inb = in + ((size_t)b * CIN + kc) * Mtot + m0;
        const float* inb2 = in2 ? in2 + ((size_t)b * CIN + kc) * Mtot + m0 : (const float*)0;
        for (int i = tid; i < 96 * 32; i += 256) {
            int kk = i >> 5, p4 = i & 31;
            float4 v = ((const float4*)(inb + (size_t)kk * Mtot))[p4];
            if (in2) {
                float4 v2 = ((const float4*)(inb2 + (size_t)kk * Mtot))[p4];
                v.x = fmaxf(v.x, v2.x); v.y = fmaxf(v.y, v2.y);
                v.z = fmaxf(v.z, v2.z); v.w = fmaxf(v.w, v2.w);
            }
            if (gamma) {
                int k = kc + kk;
                float s = sc[k], h = shf[k];
                v.x = fmaxf(fmaf(v.x, s, h), 0.f);
                v.y = fmaxf(fmaf(v.y, s, h), 0.f);
                v.z = fmaxf(fmaf(v.z, s, h), 0.f);
                v.w = fmaxf(fmaf(v.w, s, h), 0.f);
            }
            ((float4*)(xs + kk * 128))[p4] = v;
        }
        __syncthreads();
#pragma unroll 8
        for (int kk = 0; kk < 96; kk++) {
            float4 xa = *(const float4*)&xs[kk * 128 + tp * 8];
            float4 xb = *(const float4*)&xs[kk * 128 + tp * 8 + 4];
            float wr[6];
#pragma unroll
            for (int ci = 0; ci < 6; ci++) wr[ci] = wsT[kk * 97 + tc * 6 + ci];
#pragma unroll
            for (int ci = 0; ci < 6; ci++) {
                acc[ci][0] = fmaf(wr[ci], xa.x, acc[ci][0]);
                acc[ci][1] = fmaf(wr[ci], xa.y, acc[ci][1]);
                acc[ci][2] = fmaf(wr[ci], xa.z, acc[ci][2]);
                acc[ci][3] = fmaf(wr[ci], xa.w, acc[ci][3]);
                acc[ci][4] = fmaf(wr[ci], xb.x, acc[ci][4]);
                acc[ci][5] = fmaf(wr[ci], xb.y, acc[ci][5]);
                acc[ci][6] = fmaf(wr[ci], xb.z, acc[ci][6]);
                acc[ci][7] = fmaf(wr[ci], xb.w, acc[ci][7]);
            }
        }
        __syncthreads();
    }

    int cbase = co0 + tc * 6;
    float gsum = 0.f, gsq = 0.f;
#pragma unroll
    for (int ci = 0; ci < 6; ci++) {
        float bv = bias[cbase + ci];
        float v0 = acc[ci][0] + bv, v1 = acc[ci][1] + bv, v2 = acc[ci][2] + bv, v3 = acc[ci][3] + bv;
        float v4 = acc[ci][4] + bv, v5 = acc[ci][5] + bv, v6 = acc[ci][6] + bv, v7 = acc[ci][7] + bv;
        float* orow = outbuf + ((size_t)b * COUTtot + cbase + ci) * Mtot + m0 + tp * 8;
        ((float4*)orow)[0] = make_float4(v0, v1, v2, v3);
        ((float4*)orow)[1] = make_float4(v4, v5, v6, v7);
        if (stats_out) {
            gsum += v0 + v1 + v2 + v3 + v4 + v5 + v6 + v7;
            gsq  += v0 * v0 + v1 * v1 + v2 * v2 + v3 * v3 + v4 * v4 + v5 * v5 + v6 * v6 + v7 * v7;
        }
    }
    if (stats_out) {
        for (int off = 16; off; off >>= 1) {
            gsum += __shfl_down_sync(0xffffffffu, gsum, off);
            gsq  += __shfl_down_sync(0xffffffffu, gsq, off);
        }
        if ((tid & 31) == 0) {
            int g = cbase / out_cpg;
            atomicAdd(&stats_out[((size_t)(b * GRP + g)) * 2 + 0], (double)gsum);
            atomicAdd(&stats_out[((size_t)(b * GRP + g)) * 2 + 1], (double)gsq);
        }
    }
}

// ---------------------------------------------------------------------------
// Final stage: inline stage-4 finalize, GN+ReLU, conv 96->96, L2-normalize
// ---------------------------------------------------------------------------
__global__ void __launch_bounds__(256, 2)
final_kernel(const float* __restrict__ in, const float* __restrict__ w,
             const float* __restrict__ bias, const float* __restrict__ gamma,
             const float* __restrict__ beta,
             const double* __restrict__ stats4, double invcnt,
             float* __restrict__ out) {
    extern __shared__ float fsm[];
    float* xs  = fsm;
    float* wsT = fsm + 96 * 128;
    float* sc  = wsT + 96 * 97;
    float* shf = sc + 192;

    int b = blockIdx.y;
    int m0 = blockIdx.x * 128;
    int tid = threadIdx.x;
    int tc = tid >> 4, tp = tid & 15;

    for (int k = tid; k < 96; k += 256)
        gn_const(stats4, invcnt, b, k / 12, gamma, beta, k, &sc[k], &shf[k]);
    __syncthreads();
    for (int i = tid; i < 96 * 96; i += 256) {
        int c = i / 96, kk = i % 96;
        wsT[kk * 97 + c] = w[(size_t)c * 96 + kk];
    }
    const float* inb = in + (size_t)b * 96 * NPTS + m0;
    for (int i = tid; i < 96 * 32; i += 256) {
        int kk = i >> 5, p4 = i & 31;
        float4 v = ((const float4*)(inb + (size_t)kk * NPTS))[p4];
        float s = sc[kk], h = shf[kk];
        v.x = fmaxf(fmaf(v.x, s, h), 0.f);
        v.y = fmaxf(fmaf(v.y, s, h), 0.f);
        v.z = fmaxf(fmaf(v.z, s, h), 0.f);
        v.w = fmaxf(fmaf(v.w, s, h), 0.f);
        ((float4*)(xs + kk * 128))[p4] = v;
    }
    __syncthreads();

    float acc[6][8];
#pragma unroll
    for (int ci = 0; ci < 6; ci++)
#pragma unroll
        for (int pi = 0; pi < 8; pi++) acc[ci][pi] = 0.f;
#pragma unroll 8
    for (int kk = 0; kk < 96; kk++) {
        float4 xa = *(const float4*)&xs[kk * 128 + tp * 8];
        float4 xb = *(const float4*)&xs[kk * 128 + tp * 8 + 4];
        float wr[6];
#pragma unroll
        for (int ci = 0; ci < 6; ci++) wr[ci] = wsT[kk * 97 + tc * 6 + ci];
#pragma unroll
        for (int ci = 0; ci < 6; ci++) {
            acc[ci][0] = fmaf(wr[ci], xa.x, acc[ci][0]);
            acc[ci][1] = fmaf(wr[ci], xa.y, acc[ci][1]);
            acc[ci][2] = fmaf(wr[ci], xa.z, acc[ci][2]);
            acc[ci][3] = fmaf(wr[ci], xa.w, acc[ci][3]);
            acc[ci][4] = fmaf(wr[ci], xb.x, acc[ci][4]);
            acc[ci][5] = fmaf(wr[ci], xb.y, acc[ci][5]);
            acc[ci][6] = fmaf(wr[ci], xb.z, acc[ci][6]);
            acc[ci][7] = fmaf(wr[ci], xb.w, acc[ci][7]);
        }
    }
    __syncthreads();

    float* ob = fsm;
#pragma unroll
    for (int ci = 0; ci < 6; ci++) {
        float bv = bias[tc * 6 + ci];
#pragma unroll
        for (int pi = 0; pi < 8; pi++)
            ob[(tc * 6 + ci) * 129 + tp * 8 + pi] = acc[ci][pi] + bv;
    }
    __syncthreads();

    if (tid < 128) {
        int p = tid;
        float s2 = 0.f;
#pragma unroll
        for (int c = 0; c < 96; c++) {
            float v = ob[c * 129 + p];
            s2 += v * v;
        }
        float rinv = rsqrtf(s2);
        float* op = out + ((size_t)b * NPTS + m0 + p) * 96;
#pragma unroll
        for (int c = 0; c < 96; c++) op[c] = ob[c * 129 + p] * rinv;
    }
}

// ---------------------------------------------------------------------------
// Launch: ball(1) conv1(2) conv2(3) dummy(4) dummy(5) conv3(6) post1 post2 final
// ---------------------------------------------------------------------------
extern "C" void kernel_launch(void* const* d_in, const int* in_sizes, int n_in,
                              void* d_out, int out_size) {
    const float* xyz     = (const float*)d_in[0];
    const float* pre_w1  = (const float*)d_in[1];
    const float* pre_b1  = (const float*)d_in[2];
    const float* pre_g1  = (const float*)d_in[3];
    const float* pre_be1 = (const float*)d_in[4];
    const float* pre_w2  = (const float*)d_in[5];
    const float* pre_b2  = (const float*)d_in[6];
    const float* pre_g2  = (const float*)d_in[7];
    const float* pre_be2 = (const float*)d_in[8];
    const float* pre_w3  = (const float*)d_in[9];
    const float* pre_b3  = (const float*)d_in[10];
    const float* pre_g3  = (const float*)d_in[11];
    const float* pre_be3 = (const float*)d_in[12];
    const float* post_w1 = (const float*)d_in[13];
    const float* post_b1 = (const float*)d_in[14];
    const float* post_g1 = (const float*)d_in[15];
    const float* post_be1= (const float*)d_in[16];
    const float* post_w2 = (const float*)d_in[17];
    const float* post_b2 = (const float*)d_in[18];
    const float* post_g2 = (const float*)d_in[19];
    const float* post_be2= (const float*)d_in[20];
    const float* post_w3 = (const float*)d_in[21];
    const float* post_b3 = (const float*)d_in[22];
    float* out = (float*)d_out;

    double* statsP;
    float *h2P, *ppP, *p1P, *p2P;
    cudaGetSymbolAddress((void**)&statsP, d_stats);
    cudaGetSymbolAddress((void**)&h2P,    d_h2);
    cudaGetSymbolAddress((void**)&ppP,    d_poolpart);
    cudaGetSymbolAddress((void**)&p1P,    d_p1);
    cudaGetSymbolAddress((void**)&p2P,    d_p2);

    const int FSMEM = (96 * 128 + 96 * 97 + 2 * 192) * (int)sizeof(float); // 87936
    cudaFuncSetAttribute(mlp_gemm,     cudaFuncAttributeMaxDynamicSharedMemorySize, FSMEM);
    cudaFuncSetAttribute(final_kernel, cudaFuncAttributeMaxDynamicSharedMemorySize, FSMEM);
    cudaFuncSetAttribute(conv2_mma,    cudaFuncAttributeMaxDynamicSharedMemorySize, C2_SMEM);
    cudaFuncSetAttribute(conv3_mma,    cudaFuncAttributeMaxDynamicSharedMemorySize, C3_SMEM);

    const int SOFF = BATCH * GRP * 2;
    const double inv0 = 1.0 / (12.0 * MPOS);
    const double inv1 = 1.0 / (12.0 * MPOS);
    const double inv2 = 1.0 / (24.0 * MPOS);
    const double inv3 = 1.0 / (24.0 * NPTS);
    const double inv4 = 1.0 / (12.0 * NPTS);

    ballquery_kernel<<<512, 256>>>(xyz);                                   // 1
    conv1_stats_kernel<<<(BATCH * MPOS) / 256, 256>>>(                     // 2
        xyz, pre_w1, pre_b1, statsP + 0 * SOFF);

    conv2_mma<<<dim3(74, BATCH), 256, C2_SMEM>>>(                          // 3
        xyz, pre_w1, pre_b1, pre_w2, pre_b2,
        pre_g1, pre_be1, statsP + 0 * SOFF, inv0, statsP + 1 * SOFF, h2P);

    dummy_kernel<<<1, 32>>>();                                             // 4
    dummy_kernel<<<1, 32>>>();                                             // 5

    conv3_mma<<<dim3(32, BATCH, 2), 256, C3_SMEM>>>(                       // 6  <- ncu target
        h2P, pre_w3, pre_b3, pre_g2, pre_be2,
        statsP + 1 * SOFF, inv1, statsP + 2 * SOFF, ppP);

    // post1: pool-merge + GN2+ReLU + 192->192, stats -> stage3
    mlp_gemm<<<dim3(NPTS / 128, BATCH, 2), 256, FSMEM>>>(                  // 7
        ppP, ppP + (size_t)BATCH * C3 * NPTS, post_w1, post_b1, p1P,
        192, 192, NPTS, pre_g3, pre_be3, statsP + 2 * SOFF, inv2, 24,
        statsP + 3 * SOFF, 24);

    // post2: GN3+ReLU + 192->96, stats -> stage4
    mlp_gemm<<<dim3(NPTS / 128, BATCH, 1), 256, FSMEM>>>(                  // 8
        p1P, (const float*)0, post_w2, post_b2, p2P,
        192, 96, NPTS, post_g1, post_be1, statsP + 3 * SOFF, inv3, 24,
        statsP + 4 * SOFF, 12);

    final_kernel<<<dim3(NPTS / 128, BATCH, 1), 256, FSMEM>>>(              // 9
        p2P, post_w3, post_b3, post_g2, post_be2,
        statsP + 4 * SOFF, inv4, out);
}